// round 2
// baseline (speedup 1.0000x reference)
#include <cuda_runtime.h>
#include <cstdint>

#define BATCH   4096
#define DM      1024
#define DS      16384
#define K_SEL   131072           // 32 * 4096
#define H_TOTAL 67108864         // 4096 * 16384
#define CAND_CAP (4*1024*1024)
#define BCAP    8192             // boundary-set capacity
#define EPSW    2e-3f            // boundary half-window around fp32 threshold

// ------------------------- device scratch (no allocs allowed) ----------------
__device__ float          g_h[H_TOTAL];          // 256 MB scratch for h_pre
__device__ float          g_cand_val[CAND_CAP];
__device__ int            g_cand_idx[CAND_CAP];
__device__ unsigned int   g_hist[2048];
__device__ unsigned int   g_ncand;
__device__ unsigned int   g_bin_lo;              // uint lower edge (one bin below boundary bin)
__device__ float          g_hi, g_lo;            // boundary window [lo, hi]
__device__ unsigned int   g_c_in;                // count of sure-in elements
__device__ unsigned int   g_b_cnt;               // boundary count
__device__ int            g_b_idx[BCAP];
__device__ float          g_b_f32[BCAP];
__device__ double         g_b_v64[BCAP];

// ------------------------- reset ---------------------------------------------
__global__ void k_reset() {
    int i = blockIdx.x * blockDim.x + threadIdx.x;
    if (i < 2048) g_hist[i] = 0;
    if (i == 0) { g_ncand = 0; g_c_in = 0; g_b_cnt = 0; }
}

// ------------------------- encode GEMM + |h| histogram -----------------------
// C[4096,16384] = A[4096,1024] @ B[1024,16384] + bias, fp32, sequential-k FMA
__global__ __launch_bounds__(256, 2)
void k_gemm(const float* __restrict__ A, const float* __restrict__ B,
            const float* __restrict__ bias) {
    __shared__ float As[2][8][128];
    __shared__ float Bs[2][8][128];
    __shared__ unsigned int shist[2048];

    int tid = threadIdx.x;
    for (int i = tid; i < 2048; i += 256) shist[i] = 0;

    const int m0 = blockIdx.y * 128;
    const int n0 = blockIdx.x * 128;

    const int arow = tid >> 1;            // 0..127
    const int acol = (tid & 1) * 4;       // 0 or 4
    const int brow = tid >> 5;            // 0..7
    const int bcol = (tid & 31) * 4;      // 0..124

    const float* Aptr = A + (size_t)(m0 + arow) * DM + acol;
    const float* Bptr = B + (size_t)brow * DS + n0 + bcol;

    float acc[8][8];
#pragma unroll
    for (int i = 0; i < 8; i++)
#pragma unroll
        for (int j = 0; j < 8; j++) acc[i][j] = 0.0f;

    float4 a4 = *(const float4*)Aptr;
    float4 b4 = *(const float4*)Bptr;
    As[0][acol + 0][arow] = a4.x;
    As[0][acol + 1][arow] = a4.y;
    As[0][acol + 2][arow] = a4.z;
    As[0][acol + 3][arow] = a4.w;
    *(float4*)&Bs[0][brow][bcol] = b4;
    __syncthreads();

    const int ty = tid >> 4;   // 0..15
    const int tx = tid & 15;   // 0..15

    for (int kt = 1; kt <= DM / 8; ++kt) {
        const int cur = (kt - 1) & 1;
        const int nxt = kt & 1;
        if (kt < DM / 8) {
            a4 = *(const float4*)(Aptr + kt * 8);
            b4 = *(const float4*)(Bptr + (size_t)kt * 8 * DS);
        }
#pragma unroll
        for (int kk = 0; kk < 8; ++kk) {
            float a[8], b[8];
#pragma unroll
            for (int i = 0; i < 8; i++) a[i] = As[cur][kk][ty * 8 + i];
#pragma unroll
            for (int j = 0; j < 8; j++) b[j] = Bs[cur][kk][tx * 8 + j];
#pragma unroll
            for (int i = 0; i < 8; i++)
#pragma unroll
                for (int j = 0; j < 8; j++) acc[i][j] += a[i] * b[j];
        }
        if (kt < DM / 8) {
            As[nxt][acol + 0][arow] = a4.x;
            As[nxt][acol + 1][arow] = a4.y;
            As[nxt][acol + 2][arow] = a4.z;
            As[nxt][acol + 3][arow] = a4.w;
            *(float4*)&Bs[nxt][brow][bcol] = b4;
        }
        __syncthreads();
    }

    float bv[8];
#pragma unroll
    for (int j = 0; j < 8; j++) bv[j] = bias[n0 + tx * 8 + j];

#pragma unroll
    for (int i = 0; i < 8; i++) {
        const int row = m0 + ty * 8 + i;
        float v[8];
#pragma unroll
        for (int j = 0; j < 8; j++) {
            v[j] = acc[i][j] + bv[j];
            unsigned int u = __float_as_uint(fabsf(v[j]));
            atomicAdd(&shist[u >> 21], 1u);
        }
        float* cp = g_h + (size_t)row * DS + n0 + tx * 8;
        *(float4*)(cp + 0) = make_float4(v[0], v[1], v[2], v[3]);
        *(float4*)(cp + 4) = make_float4(v[4], v[5], v[6], v[7]);
    }

    __syncthreads();
    for (int i = tid; i < 2048; i += 256)
        if (shist[i]) atomicAdd(&g_hist[i], shist[i]);
}

// ------------------------- scan histogram: coarse bin (minus one for margin) --
__global__ void k_scan_hist() {
    unsigned long long cum = 0;
    int b = 0;
    for (b = 2047; b >= 0; --b) {
        cum += g_hist[b];
        if (cum >= (unsigned long long)K_SEL) break;
    }
    b = b - 1;                 // one bin lower: window [T-eps, T] stays inside candidates
    if (b < 0) b = 0;
    g_bin_lo = ((unsigned int)b) << 21;
}

// ------------------------- collect candidates --------------------------------
__global__ void k_collect() {
    const unsigned int lo = g_bin_lo;
    const int stride = gridDim.x * blockDim.x * 4;
    int i = (blockIdx.x * blockDim.x + threadIdx.x) * 4;
    for (; i < H_TOTAL; i += stride) {
        float4 v4 = *(const float4*)(g_h + i);
        float vv[4] = {v4.x, v4.y, v4.z, v4.w};
#pragma unroll
        for (int e = 0; e < 4; e++) {
            unsigned int u = __float_as_uint(fabsf(vv[e]));
            if (u >= lo) {
                unsigned int pos = atomicAdd(&g_ncand, 1u);
                if (pos < CAND_CAP) {
                    g_cand_val[pos] = vv[e];
                    g_cand_idx[pos] = i + e;
                }
            }
        }
    }
}

// ------------------------- exact k-th fp32 |h| via radix select ---------------
__global__ __launch_bounds__(1024)
void k_select() {
    __shared__ unsigned int sh[2048];
    __shared__ unsigned int s_prefix, s_mask, s_remaining;

    const int tid = threadIdx.x;
    const int n = min(g_ncand, (unsigned int)CAND_CAP);

    if (tid == 0) { s_prefix = 0; s_mask = 0; s_remaining = K_SEL; }
    __syncthreads();

    const int shifts[3] = {21, 10, 0};
    const int widths[3] = {11, 11, 10};

    for (int c = 0; c < 3; c++) {
        for (int i = tid; i < 2048; i += 1024) sh[i] = 0;
        __syncthreads();
        const unsigned int pre = s_prefix, msk = s_mask;
        const int sft = shifts[c];
        const unsigned int wm = (1u << widths[c]) - 1u;
        for (int i = tid; i < n; i += 1024) {
            unsigned int u = __float_as_uint(fabsf(g_cand_val[i]));
            if ((u & msk) == pre) atomicAdd(&sh[(u >> sft) & wm], 1u);
        }
        __syncthreads();
        if (tid == 0) {
            unsigned long long cum = 0;
            int b;
            for (b = (int)wm; b >= 0; --b) {
                if (cum + sh[b] >= (unsigned long long)s_remaining) break;
                cum += sh[b];
            }
            if (b < 0) b = 0;
            s_remaining -= (unsigned int)cum;
            s_prefix |= ((unsigned int)b) << sft;
            s_mask   |= wm << sft;
        }
        __syncthreads();
    }

    if (tid == 0) {
        const float t = __uint_as_float(s_prefix);   // exact fp32 k-th |h|
        g_hi = t + EPSW;
        g_lo = t - EPSW;
    }
}

// ------------------------- classify + scatter sure-in -------------------------
// sure-in:  |v| >= hi  -> count + write to fx directly
// boundary: lo < |v| < hi -> collect for fp64 re-ranking
__global__ void k_classify(float* __restrict__ fx) {
    const float hi = g_hi, lo = g_lo;
    const int n = min(g_ncand, (unsigned int)CAND_CAP);
    const int stride = gridDim.x * blockDim.x;
    for (int i = blockIdx.x * blockDim.x + threadIdx.x; i < n; i += stride) {
        const float v = g_cand_val[i];
        const float a = fabsf(v);
        if (a >= hi) {
            atomicAdd(&g_c_in, 1u);
            fx[g_cand_idx[i]] = v;
        } else if (a > lo) {
            unsigned int p = atomicAdd(&g_b_cnt, 1u);
            if (p < BCAP) { g_b_idx[p] = g_cand_idx[i]; g_b_f32[p] = v; }
        }
    }
}

// ------------------------- fp64 exact recompute of boundary dots --------------
// one warp per boundary element: lane-strided fp64 accumulation + shfl reduce
__global__ __launch_bounds__(256)
void k_exact(const float* __restrict__ A, const float* __restrict__ B,
             const float* __restrict__ bias) {
    const int n = min(g_b_cnt, (unsigned int)BCAP);
    const int warps = (gridDim.x * blockDim.x) >> 5;
    const int wid = (blockIdx.x * blockDim.x + threadIdx.x) >> 5;
    const int lane = threadIdx.x & 31;
    for (int e = wid; e < n; e += warps) {
        const int idx = g_b_idx[e];
        const int row = idx >> 14;          // / DS
        const int col = idx & (DS - 1);
        const float* __restrict__ xr = A + (size_t)row * DM;
        double s = 0.0;
        for (int m = lane; m < DM; m += 32)
            s += (double)xr[m] * (double)B[(size_t)m * DS + col];
#pragma unroll
        for (int off = 16; off > 0; off >>= 1)
            s += __shfl_down_sync(0xffffffffu, s, off);
        if (lane == 0) g_b_v64[e] = fabs(s + (double)bias[col]);
    }
}

// ------------------------- rank boundary, accept K - C_in, scatter ------------
__global__ __launch_bounds__(1024)
void k_accept(float* __restrict__ fx) {
    const int n = min(g_b_cnt, (unsigned int)BCAP);
    const unsigned int kp = K_SEL - g_c_in;     // how many boundary elems to accept
    for (int i = threadIdx.x; i < n; i += 1024) {
        const double vi = g_b_v64[i];
        const int    ii = g_b_idx[i];
        unsigned int rank = 0;
        for (int j = 0; j < n; j++) {
            const double vj = g_b_v64[j];
            rank += (vj > vi) || (vj == vi && g_b_idx[j] < ii);
        }
        if (rank < kp) fx[ii] = g_b_f32[i];
    }
}

// ------------------------- sparse decode -------------------------------------
__global__ __launch_bounds__(256)
void k_decode(const float* __restrict__ fx, const float* __restrict__ Wd,
              const float* __restrict__ bdec, float* __restrict__ xhat) {
    __shared__ float svals[2048];
    __shared__ int   scols[2048];
    __shared__ unsigned int wcnt[8];
    __shared__ unsigned int scnt;

    const int b = blockIdx.x;
    const int tid = threadIdx.x;
    const int warp = tid >> 5, lane = tid & 31;

    float4 acc = *(const float4*)(bdec + tid * 4);
    const float* row = fx + (size_t)b * DS;

    for (int seg = 0; seg < DS; seg += 2048) {
        if (tid == 0) scnt = 0;
        __syncthreads();
        for (int sub = 0; sub < 2048; sub += 256) {
            const int c = seg + sub + tid;
            const float v = row[c];
            const unsigned int m = __ballot_sync(0xffffffffu, v != 0.0f);
            if (lane == 0) wcnt[warp] = __popc(m);
            __syncthreads();
            if (tid == 0) {
                unsigned int s = scnt;
                for (int w = 0; w < 8; w++) { unsigned int t = wcnt[w]; wcnt[w] = s; s += t; }
                scnt = s;
            }
            __syncthreads();
            if (v != 0.0f) {
                unsigned int p = wcnt[warp] + __popc(m & ((1u << lane) - 1u));
                svals[p] = v;
                scols[p] = c;
            }
            __syncthreads();
        }
        const int cnt = (int)scnt;
        int i = 0;
        for (; i + 4 <= cnt; i += 4) {
            const int s0 = scols[i], s1 = scols[i + 1], s2 = scols[i + 2], s3 = scols[i + 3];
            const float v0 = svals[i], v1 = svals[i + 1], v2 = svals[i + 2], v3 = svals[i + 3];
            const float4 w0 = *(const float4*)(Wd + (size_t)s0 * DM + tid * 4);
            const float4 w1 = *(const float4*)(Wd + (size_t)s1 * DM + tid * 4);
            const float4 w2 = *(const float4*)(Wd + (size_t)s2 * DM + tid * 4);
            const float4 w3 = *(const float4*)(Wd + (size_t)s3 * DM + tid * 4);
            acc.x += v0 * w0.x; acc.y += v0 * w0.y; acc.z += v0 * w0.z; acc.w += v0 * w0.w;
            acc.x += v1 * w1.x; acc.y += v1 * w1.y; acc.z += v1 * w1.z; acc.w += v1 * w1.w;
            acc.x += v2 * w2.x; acc.y += v2 * w2.y; acc.z += v2 * w2.z; acc.w += v2 * w2.w;
            acc.x += v3 * w3.x; acc.y += v3 * w3.y; acc.z += v3 * w3.z; acc.w += v3 * w3.w;
        }
        for (; i < cnt; ++i) {
            const int s0 = scols[i];
            const float v0 = svals[i];
            const float4 w0 = *(const float4*)(Wd + (size_t)s0 * DM + tid * 4);
            acc.x += v0 * w0.x; acc.y += v0 * w0.y; acc.z += v0 * w0.z; acc.w += v0 * w0.w;
        }
        __syncthreads();
    }
    *(float4*)(xhat + (size_t)b * DM + tid * 4) = acc;
}

// ------------------------- host launcher -------------------------------------
extern "C" void kernel_launch(void* const* d_in, const int* in_sizes, int n_in,
                              void* d_out, int out_size) {
    const float* x     = (const float*)d_in[0];   // [4096,1024]
    const float* W_enc = (const float*)d_in[1];   // [1024,16384]
    const float* b_enc = (const float*)d_in[2];   // [16384]
    const float* W_dec = (const float*)d_in[3];   // [16384,1024]
    const float* b_dec = (const float*)d_in[4];   // [1024]

    float* out  = (float*)d_out;
    float* xhat = out;                            // first 4096*1024 floats

    static float* g_h_ptr = nullptr;
    if (!g_h_ptr) cudaGetSymbolAddress((void**)&g_h_ptr, g_h);

    const long long want = (long long)BATCH * DM + (long long)H_TOTAL;
    float* fx = ((long long)out_size >= want) ? (out + (size_t)BATCH * DM) : g_h_ptr;

    k_reset<<<8, 256>>>();
    {
        dim3 grid(DS / 128, BATCH / 128);
        k_gemm<<<grid, 256>>>(x, W_enc, b_enc);
    }
    k_scan_hist<<<1, 1>>>();
    k_collect<<<8192, 256>>>();
    k_select<<<1, 1024>>>();
    cudaMemsetAsync(fx, 0, (size_t)H_TOTAL * sizeof(float), 0);
    k_classify<<<1024, 256>>>(fx);
    k_exact<<<512, 256>>>(x, W_enc, b_enc);
    k_accept<<<1, 1024>>>(fx);
    k_decode<<<BATCH, 256>>>(fx, W_dec, b_dec, xhat);
}

// round 3
// speedup vs baseline: 1.2509x; 1.2509x over previous
#include <cuda_runtime.h>
#include <cstdint>

#define BATCH   4096
#define DM      1024
#define DS      16384
#define K_SEL   131072           // 32 * 4096
#define H_TOTAL 67108864         // 4096 * 16384
#define CAND_CAP (4*1024*1024)
#define CAND_T  3.0f             // static candidate threshold (k-th |h| ~ 4.32)
#define BCAP    8192             // boundary-set capacity
#define NOISE   1.5e-4f          // fp32 accumulation-noise margin
#define ROWCAP  96               // per-row CSR capacity (mean 32, 11 sigma safe)
#define BLK_CAND_CAP 1024        // per-CTA epilogue candidate buffer

// ------------------------- device scratch (no allocs allowed) ----------------
__device__ float          g_fx_fallback[H_TOTAL];   // used only if out buffer too small
__device__ float          g_cand_val[CAND_CAP];
__device__ int            g_cand_idx[CAND_CAP];
__device__ unsigned int   g_hist1[2048];
__device__ unsigned int   g_hist2[2048];
__device__ unsigned int   g_ncand;
__device__ unsigned int   g_b1;                  // selected coarse bin
__device__ unsigned int   g_rem1;                // remaining rank within bin b1
__device__ float          g_hi, g_lo;            // boundary window
__device__ unsigned int   g_c_in;                // count of sure-in elements
__device__ unsigned int   g_b_cnt;               // boundary count
__device__ int            g_b_idx[BCAP];
__device__ float          g_b_f32[BCAP];
__device__ double         g_b_v64[BCAP];
__device__ unsigned int   g_row_cnt[BATCH];      // CSR row counts
__device__ int            g_row_col[BATCH * ROWCAP];
__device__ float          g_row_val[BATCH * ROWCAP];

// ------------------------- reset ---------------------------------------------
__global__ void k_reset() {
    int i = blockIdx.x * blockDim.x + threadIdx.x;
    if (i < 2048) { g_hist1[i] = 0; g_hist2[i] = 0; }
    if (i < BATCH) g_row_cnt[i] = 0;
    if (i == 0) { g_ncand = 0; g_c_in = 0; g_b_cnt = 0; }
}

// ------------------------- encode GEMM + fused candidate collection ----------
// C[4096,16384] = A[4096,1024] @ B[1024,16384] + bias, fp32 FFMA.
// Epilogue: |v| >= CAND_T -> block-local list -> ONE global atomic per CTA.
__global__ __launch_bounds__(256, 2)
void k_gemm_cand(const float* __restrict__ A, const float* __restrict__ B,
                 const float* __restrict__ bias) {
    __shared__ float As[2][8][128];
    __shared__ float Bs[2][8][128];
    __shared__ float s_cval[BLK_CAND_CAP];
    __shared__ int   s_cidx[BLK_CAND_CAP];
    __shared__ unsigned int s_cnt, s_base;

    int tid = threadIdx.x;
    if (tid == 0) s_cnt = 0;

    const int m0 = blockIdx.y * 128;
    const int n0 = blockIdx.x * 128;

    const int arow = tid >> 1;            // 0..127
    const int acol = (tid & 1) * 4;       // 0 or 4
    const int brow = tid >> 5;            // 0..7
    const int bcol = (tid & 31) * 4;      // 0..124

    const float* Aptr = A + (size_t)(m0 + arow) * DM + acol;
    const float* Bptr = B + (size_t)brow * DS + n0 + bcol;

    float acc[8][8];
#pragma unroll
    for (int i = 0; i < 8; i++)
#pragma unroll
        for (int j = 0; j < 8; j++) acc[i][j] = 0.0f;

    float4 a4 = *(const float4*)Aptr;
    float4 b4 = *(const float4*)Bptr;
    As[0][acol + 0][arow] = a4.x;
    As[0][acol + 1][arow] = a4.y;
    As[0][acol + 2][arow] = a4.z;
    As[0][acol + 3][arow] = a4.w;
    *(float4*)&Bs[0][brow][bcol] = b4;
    __syncthreads();

    const int ty = tid >> 4;   // 0..15
    const int tx = tid & 15;   // 0..15

    for (int kt = 1; kt <= DM / 8; ++kt) {
        const int cur = (kt - 1) & 1;
        const int nxt = kt & 1;
        if (kt < DM / 8) {
            a4 = *(const float4*)(Aptr + kt * 8);
            b4 = *(const float4*)(Bptr + (size_t)kt * 8 * DS);
        }
#pragma unroll
        for (int kk = 0; kk < 8; ++kk) {
            float a[8], b[8];
#pragma unroll
            for (int i = 0; i < 8; i++) a[i] = As[cur][kk][ty * 8 + i];
#pragma unroll
            for (int j = 0; j < 8; j++) b[j] = Bs[cur][kk][tx * 8 + j];
#pragma unroll
            for (int i = 0; i < 8; i++)
#pragma unroll
                for (int j = 0; j < 8; j++) acc[i][j] += a[i] * b[j];
        }
        if (kt < DM / 8) {
            As[nxt][acol + 0][arow] = a4.x;
            As[nxt][acol + 1][arow] = a4.y;
            As[nxt][acol + 2][arow] = a4.z;
            As[nxt][acol + 3][arow] = a4.w;
            *(float4*)&Bs[nxt][brow][bcol] = b4;
        }
        __syncthreads();
    }

    // epilogue: bias add + candidate collection (no dense h store)
    float bv[8];
#pragma unroll
    for (int j = 0; j < 8; j++) bv[j] = bias[n0 + tx * 8 + j];

#pragma unroll
    for (int i = 0; i < 8; i++) {
        const int row = m0 + ty * 8 + i;
#pragma unroll
        for (int j = 0; j < 8; j++) {
            const float v = acc[i][j] + bv[j];
            if (fabsf(v) >= CAND_T) {
                unsigned int p = atomicAdd(&s_cnt, 1u);
                if (p < BLK_CAND_CAP) {
                    s_cval[p] = v;
                    s_cidx[p] = (row << 14) + n0 + tx * 8 + j;
                }
            }
        }
    }
    __syncthreads();
    if (tid == 0) {
        unsigned int cnt = min(s_cnt, (unsigned int)BLK_CAND_CAP);
        s_base = atomicAdd(&g_ncand, cnt);
        s_cnt = cnt;
    }
    __syncthreads();
    const unsigned int cnt = s_cnt, base = s_base;
    for (unsigned int i = tid; i < cnt; i += 256) {
        const unsigned int p = base + i;
        if (p < CAND_CAP) { g_cand_val[p] = s_cval[i]; g_cand_idx[p] = s_cidx[i]; }
    }
}

// ------------------------- radix pass 1: top-11 bits -------------------------
__global__ __launch_bounds__(256)
void k_hist1() {
    __shared__ unsigned int sh[2048];
    for (int i = threadIdx.x; i < 2048; i += 256) sh[i] = 0;
    __syncthreads();
    const int n = min(g_ncand, (unsigned int)CAND_CAP);
    const int stride = gridDim.x * blockDim.x;
    for (int i = blockIdx.x * blockDim.x + threadIdx.x; i < n; i += stride) {
        unsigned int u = __float_as_uint(fabsf(g_cand_val[i]));
        atomicAdd(&sh[u >> 21], 1u);
    }
    __syncthreads();
    for (int i = threadIdx.x; i < 2048; i += 256)
        if (sh[i]) atomicAdd(&g_hist1[i], sh[i]);
}

__global__ void k_scan1() {
    unsigned long long cum = 0;
    int b;
    for (b = 2047; b >= 0; --b) {
        if (cum + g_hist1[b] >= (unsigned long long)K_SEL) break;
        cum += g_hist1[b];
    }
    if (b < 0) b = 0;
    g_b1 = (unsigned int)b;
    g_rem1 = K_SEL - (unsigned int)cum;   // rank to find inside bin b
}

// ------------------------- radix pass 2: next 11 bits ------------------------
__global__ __launch_bounds__(256)
void k_hist2() {
    __shared__ unsigned int sh[2048];
    for (int i = threadIdx.x; i < 2048; i += 256) sh[i] = 0;
    __syncthreads();
    const unsigned int b1 = g_b1;
    const int n = min(g_ncand, (unsigned int)CAND_CAP);
    const int stride = gridDim.x * blockDim.x;
    for (int i = blockIdx.x * blockDim.x + threadIdx.x; i < n; i += stride) {
        unsigned int u = __float_as_uint(fabsf(g_cand_val[i]));
        if ((u >> 21) == b1) atomicAdd(&sh[(u >> 10) & 0x7FF], 1u);
    }
    __syncthreads();
    for (int i = threadIdx.x; i < 2048; i += 256)
        if (sh[i]) atomicAdd(&g_hist2[i], sh[i]);
}

__global__ void k_scan2() {
    const unsigned int rem = g_rem1;
    unsigned long long cum = 0;
    int b;
    for (b = 2047; b >= 0; --b) {
        cum += g_hist2[b];
        if (cum >= (unsigned long long)rem) break;
    }
    if (b < 0) b = 0;
    const unsigned int Tf_u = (g_b1 << 21) | ((unsigned int)b << 10);
    const float Tlo = __uint_as_float(Tf_u);          // k-th |h| is in [Tlo, Tnext)
    const float Tnext = __uint_as_float(Tf_u + 1024);
    g_lo = Tlo - NOISE;
    g_hi = Tnext + NOISE;
}

// ------------------------- classify: sure-in / boundary ----------------------
__global__ __launch_bounds__(256)
void k_classify(float* __restrict__ fx) {
    __shared__ unsigned int s_in;
    if (threadIdx.x == 0) s_in = 0;
    __syncthreads();
    const float hi = g_hi, lo = g_lo;
    const int n = min(g_ncand, (unsigned int)CAND_CAP);
    const int stride = gridDim.x * blockDim.x;
    for (int i = blockIdx.x * blockDim.x + threadIdx.x; i < n; i += stride) {
        const float v = g_cand_val[i];
        const float a = fabsf(v);
        if (a >= hi) {
            atomicAdd(&s_in, 1u);
            const int idx = g_cand_idx[i];
            fx[idx] = v;
            const int row = idx >> 14;
            unsigned int slot = atomicAdd(&g_row_cnt[row], 1u);
            if (slot < ROWCAP) {
                g_row_col[row * ROWCAP + slot] = idx & (DS - 1);
                g_row_val[row * ROWCAP + slot] = v;
            }
        } else if (a > lo) {
            unsigned int p = atomicAdd(&g_b_cnt, 1u);
            if (p < BCAP) { g_b_idx[p] = g_cand_idx[i]; g_b_f32[p] = v; }
        }
    }
    __syncthreads();
    if (threadIdx.x == 0 && s_in) atomicAdd(&g_c_in, s_in);
}

// ------------------------- fp64 exact recompute of boundary dots --------------
__global__ __launch_bounds__(256)
void k_exact(const float* __restrict__ A, const float* __restrict__ B,
             const float* __restrict__ bias) {
    const int n = min(g_b_cnt, (unsigned int)BCAP);
    const int warps = (gridDim.x * blockDim.x) >> 5;
    const int wid = (blockIdx.x * blockDim.x + threadIdx.x) >> 5;
    const int lane = threadIdx.x & 31;
    for (int e = wid; e < n; e += warps) {
        const int idx = g_b_idx[e];
        const int row = idx >> 14;
        const int col = idx & (DS - 1);
        const float* __restrict__ xr = A + (size_t)row * DM;
        double s = 0.0;
        for (int m = lane; m < DM; m += 32)
            s += (double)xr[m] * (double)B[(size_t)m * DS + col];
#pragma unroll
        for (int off = 16; off > 0; off >>= 1)
            s += __shfl_down_sync(0xffffffffu, s, off);
        if (lane == 0) g_b_v64[e] = fabs(s + (double)bias[col]);
    }
}

// ------------------------- rank boundary, accept K - C_in ---------------------
__global__ __launch_bounds__(1024)
void k_accept(float* __restrict__ fx) {
    const int n = min(g_b_cnt, (unsigned int)BCAP);
    const unsigned int kp = K_SEL - g_c_in;
    for (int i = threadIdx.x; i < n; i += 1024) {
        const double vi = g_b_v64[i];
        const int    ii = g_b_idx[i];
        unsigned int rank = 0;
        for (int j = 0; j < n; j++) {
            const double vj = g_b_v64[j];
            rank += (vj > vi) || (vj == vi && g_b_idx[j] < ii);
        }
        if (rank < kp) {
            fx[ii] = g_b_f32[i];
            const int row = ii >> 14;
            unsigned int slot = atomicAdd(&g_row_cnt[row], 1u);
            if (slot < ROWCAP) {
                g_row_col[row * ROWCAP + slot] = ii & (DS - 1);
                g_row_val[row * ROWCAP + slot] = g_b_f32[i];
            }
        }
    }
}

// ------------------------- CSR decode ----------------------------------------
// one block per batch row; rank-sort (deterministic) then gather W_dec rows
__global__ __launch_bounds__(256)
void k_decode(const float* __restrict__ Wd, const float* __restrict__ bdec,
              float* __restrict__ xhat) {
    __shared__ int   s_col[ROWCAP];
    __shared__ float s_val[ROWCAP];
    __shared__ int   s_scol[ROWCAP];
    __shared__ float s_sval[ROWCAP];

    const int b = blockIdx.x;
    const int tid = threadIdx.x;
    const int cnt = (int)min(g_row_cnt[b], (unsigned int)ROWCAP);

    if (tid < cnt) {
        s_col[tid] = g_row_col[b * ROWCAP + tid];
        s_val[tid] = g_row_val[b * ROWCAP + tid];
    }
    __syncthreads();
    if (tid < cnt) {
        const int ci = s_col[tid];
        int rank = 0;
        for (int j = 0; j < cnt; j++) rank += (s_col[j] < ci);   // cols distinct
        s_scol[rank] = ci;
        s_sval[rank] = s_val[tid];
    }
    __syncthreads();

    float4 acc = *(const float4*)(bdec + tid * 4);
    int i = 0;
    for (; i + 4 <= cnt; i += 4) {
        const int c0 = s_scol[i], c1 = s_scol[i + 1], c2 = s_scol[i + 2], c3 = s_scol[i + 3];
        const float v0 = s_sval[i], v1 = s_sval[i + 1], v2 = s_sval[i + 2], v3 = s_sval[i + 3];
        const float4 w0 = *(const float4*)(Wd + (size_t)c0 * DM + tid * 4);
        const float4 w1 = *(const float4*)(Wd + (size_t)c1 * DM + tid * 4);
        const float4 w2 = *(const float4*)(Wd + (size_t)c2 * DM + tid * 4);
        const float4 w3 = *(const float4*)(Wd + (size_t)c3 * DM + tid * 4);
        acc.x += v0 * w0.x; acc.y += v0 * w0.y; acc.z += v0 * w0.z; acc.w += v0 * w0.w;
        acc.x += v1 * w1.x; acc.y += v1 * w1.y; acc.z += v1 * w1.z; acc.w += v1 * w1.w;
        acc.x += v2 * w2.x; acc.y += v2 * w2.y; acc.z += v2 * w2.z; acc.w += v2 * w2.w;
        acc.x += v3 * w3.x; acc.y += v3 * w3.y; acc.z += v3 * w3.z; acc.w += v3 * w3.w;
    }
    for (; i < cnt; ++i) {
        const int c0 = s_scol[i];
        const float v0 = s_sval[i];
        const float4 w0 = *(const float4*)(Wd + (size_t)c0 * DM + tid * 4);
        acc.x += v0 * w0.x; acc.y += v0 * w0.y; acc.z += v0 * w0.z; acc.w += v0 * w0.w;
    }
    *(float4*)(xhat + (size_t)b * DM + tid * 4) = acc;
}

// ------------------------- host launcher -------------------------------------
extern "C" void kernel_launch(void* const* d_in, const int* in_sizes, int n_in,
                              void* d_out, int out_size) {
    const float* x     = (const float*)d_in[0];   // [4096,1024]
    const float* W_enc = (const float*)d_in[1];   // [1024,16384]
    const float* b_enc = (const float*)d_in[2];   // [16384]
    const float* W_dec = (const float*)d_in[3];   // [16384,1024]
    const float* b_dec = (const float*)d_in[4];   // [1024]

    float* out  = (float*)d_out;
    float* xhat = out;                            // first 4096*1024 floats

    static float* g_fb_ptr = nullptr;
    if (!g_fb_ptr) cudaGetSymbolAddress((void**)&g_fb_ptr, g_fx_fallback);

    const long long want = (long long)BATCH * DM + (long long)H_TOTAL;
    float* fx = ((long long)out_size >= want) ? (out + (size_t)BATCH * DM) : g_fb_ptr;

    k_reset<<<34, 256>>>();
    {
        dim3 grid(DS / 128, BATCH / 128);
        k_gemm_cand<<<grid, 256>>>(x, W_enc, b_enc);
    }
    cudaMemsetAsync(fx, 0, (size_t)H_TOTAL * sizeof(float), 0);
    k_hist1<<<2048, 256>>>();
    k_scan1<<<1, 1>>>();
    k_hist2<<<2048, 256>>>();
    k_scan2<<<1, 1>>>();
    k_classify<<<2048, 256>>>(fx);
    k_exact<<<64, 256>>>(x, W_enc, b_enc);
    k_accept<<<1, 1024>>>(fx);
    k_decode<<<BATCH, 256>>>(W_dec, b_dec, xhat);
}

// round 5
// speedup vs baseline: 5.1683x; 4.1316x over previous
#include <cuda_runtime.h>
#include <cuda_bf16.h>
#include <cstdint>

#define BATCH   4096
#define DM      1024
#define DS      16384
#define K_SEL   131072
#define H_TOTAL 67108864
#define WCAP    (2*1024*1024)
#define NCAP    (512*1024)
#define BCAP    8192
#define NOISE   1.5e-4f
#define MARGIN  0.04f
#define CAND_T  3.5f
#define ROWCAP  96
#define BLK_CAP 1024
#define NGRP    512

// GEMM tiling (sm80-style mma.sync path; tcgen05 not available: ptx target is sm_100)
#define BM 128
#define BN 128
#define BK 64
#define A_STG 16384
#define B_STG 16384
#define OFF_A    0
#define OFF_B    32768
#define OFF_BIAS 65536
#define OFF_CV   66048
#define OFF_CI   70144
#define OFF_CNT  74240
#define OFF_BSE  74244
#define SMEM_GEMM 74368

#define SWZ(b) ((b) ^ (((b) >> 3) & 0x70))

// ------------------------- device scratch ------------------------------------
__device__ float          g_fx_fallback[H_TOTAL];
__device__ __nv_bfloat16  g_xb[BATCH * DM];
__device__ __nv_bfloat16  g_wbT[DS * DM];        // [n][k] bf16
__device__ float          g_wide_val[WCAP];
__device__ int            g_wide_idx[WCAP];
__device__ unsigned int   g_nwide;
__device__ unsigned int   g_hist1[2048];
__device__ unsigned int   g_hist2[2048];
__device__ unsigned int   g_b1, g_rem1;
__device__ float          g_Tbf;
__device__ float          g_hi, g_lo;
__device__ unsigned int   g_grp_cnt[NGRP], g_grp_cur[NGRP], g_grp_base[NGRP];
__device__ unsigned int   g_nnar;
__device__ int            g_srt_idx[NCAP];
__device__ float          g_exact_val[NCAP];
__device__ unsigned int   g_c_in, g_b_cnt;
__device__ int            g_b_idx[BCAP];
__device__ float          g_b_f32[BCAP];
__device__ double         g_b_v64[BCAP];
__device__ unsigned int   g_row_cnt[BATCH];
__device__ int            g_row_col[BATCH * ROWCAP];
__device__ float          g_row_val[BATCH * ROWCAP];

// ------------------------- PTX helpers ---------------------------------------
__device__ __forceinline__ uint32_t smem_u32(const void* p) {
    uint32_t a;
    asm("{ .reg .u64 t; cvta.to.shared.u64 t, %1; cvt.u32.u64 %0, t; }" : "=r"(a) : "l"(p));
    return a;
}
__device__ __forceinline__ void cpasync16(uint32_t dst, const void* src) {
    asm volatile("cp.async.cg.shared.global [%0], [%1], 16;" :: "r"(dst), "l"(src) : "memory");
}
__device__ __forceinline__ void cp_commit() { asm volatile("cp.async.commit_group;" ::: "memory"); }
__device__ __forceinline__ void cp_wait1()  { asm volatile("cp.async.wait_group 1;" ::: "memory"); }
__device__ __forceinline__ void cp_wait0()  { asm volatile("cp.async.wait_group 0;" ::: "memory"); }

__device__ __forceinline__ void ldsm_x4(uint32_t& r0, uint32_t& r1, uint32_t& r2, uint32_t& r3,
                                        uint32_t addr) {
    asm volatile("ldmatrix.sync.aligned.m8n8.x4.shared.b16 {%0,%1,%2,%3}, [%4];"
                 : "=r"(r0), "=r"(r1), "=r"(r2), "=r"(r3) : "r"(addr));
}
__device__ __forceinline__ void ldsm_x2(uint32_t& r0, uint32_t& r1, uint32_t addr) {
    asm volatile("ldmatrix.sync.aligned.m8n8.x2.shared.b16 {%0,%1}, [%2];"
                 : "=r"(r0), "=r"(r1) : "r"(addr));
}
__device__ __forceinline__ void mma16816(float* d, const uint32_t* a, const uint32_t* b) {
    asm volatile(
        "mma.sync.aligned.m16n8k16.row.col.f32.bf16.bf16.f32 "
        "{%0,%1,%2,%3}, {%4,%5,%6,%7}, {%8,%9}, {%0,%1,%2,%3};"
        : "+f"(d[0]), "+f"(d[1]), "+f"(d[2]), "+f"(d[3])
        : "r"(a[0]), "r"(a[1]), "r"(a[2]), "r"(a[3]), "r"(b[0]), "r"(b[1]));
}

// ------------------------- reset ---------------------------------------------
__global__ void k_reset() {
    int i = blockIdx.x * blockDim.x + threadIdx.x;
    if (i < 2048) { g_hist1[i] = 0; g_hist2[i] = 0; }
    if (i < NGRP) { g_grp_cnt[i] = 0; g_grp_cur[i] = 0; }
    if (i < BATCH) g_row_cnt[i] = 0;
    if (i == 0) { g_nwide = 0; g_nnar = 0; g_c_in = 0; g_b_cnt = 0; }
}
__global__ void k_reset2() {
    int i = blockIdx.x * blockDim.x + threadIdx.x;
    if (i < 2048) { g_hist1[i] = 0; g_hist2[i] = 0; }
}

// ------------------------- converts ------------------------------------------
__global__ void k_cvt_x(const float* __restrict__ x) {
    const int n2 = BATCH * DM / 2;
    const int stride = gridDim.x * blockDim.x;
    __nv_bfloat162* o = (__nv_bfloat162*)g_xb;
    const float2* s = (const float2*)x;
    for (int i = blockIdx.x * blockDim.x + threadIdx.x; i < n2; i += stride)
        o[i] = __float22bfloat162_rn(s[i]);
}
__global__ void k_cvt_wT(const float* __restrict__ W) {
    __shared__ float t[32][33];
    const int n0 = blockIdx.x * 32, k0 = blockIdx.y * 32;
    const int tx = threadIdx.x, ty = threadIdx.y;  // 32 x 8
#pragma unroll
    for (int i = 0; i < 4; i++)
        t[ty + 8 * i][tx] = W[(size_t)(k0 + ty + 8 * i) * DS + n0 + tx];
    __syncthreads();
#pragma unroll
    for (int i = 0; i < 4; i++)
        g_wbT[(size_t)(n0 + ty + 8 * i) * DM + k0 + tx] = __float2bfloat16(t[tx][ty + 8 * i]);
}

// ------------------------- bf16 mma.sync GEMM + screen -----------------------
__device__ __forceinline__ void load_tiles(uint32_t sb, int m0, int n0, int kt, int s, int tid) {
    const uint32_t ab = sb + OFF_A + s * A_STG;
#pragma unroll
    for (int i = 0; i < 4; i++) {
        int c = tid + i * 256;
        int row = c >> 3, chunk = c & 7;
        cpasync16(ab + SWZ((uint32_t)row * 128u + (uint32_t)chunk * 16u),
                  g_xb + (size_t)(m0 + row) * DM + kt * BK + chunk * 8);
    }
    const uint32_t bb = sb + OFF_B + s * B_STG;
#pragma unroll
    for (int i = 0; i < 4; i++) {
        int c = tid + i * 256;
        int row = c >> 3, chunk = c & 7;
        cpasync16(bb + SWZ((uint32_t)row * 128u + (uint32_t)chunk * 16u),
                  g_wbT + (size_t)(n0 + row) * DM + kt * BK + chunk * 8);
    }
    cp_commit();
}

__global__ __launch_bounds__(256, 2)
void k_gemm_bf(const float* __restrict__ bias) {
    extern __shared__ char smem[];
    const uint32_t sb = smem_u32(smem);
    const int tid = threadIdx.x, wid = tid >> 5, lane = tid & 31;
    const int m0 = blockIdx.y * BM, n0 = blockIdx.x * BN;
    const int wm = (wid & 1) * 64;     // warp m-offset
    const int wn = (wid >> 1) * 32;    // warp n-offset

    float* sh_bias = (float*)(smem + OFF_BIAS);
    if (tid < BN) sh_bias[tid] = bias[n0 + tid];
    if (tid == 0) *(unsigned*)(smem + OFF_CNT) = 0;

    float acc[4][4][4];
#pragma unroll
    for (int mf = 0; mf < 4; mf++)
#pragma unroll
        for (int nf = 0; nf < 4; nf++)
#pragma unroll
            for (int r = 0; r < 4; r++) acc[mf][nf][r] = 0.f;

    load_tiles(sb, m0, n0, 0, 0, tid);
    load_tiles(sb, m0, n0, 1, 1, tid);

    // ldmatrix lane addressing (fixed per thread)
    const int a_row = (lane & 15);          // row within 16-row frag
    const int a_chk = (lane >> 4);          // 16B chunk within k16
    const int b_row = (lane & 7);
    const int b_chk = ((lane >> 3) & 1);

    for (int kt = 0; kt < DM / BK; ++kt) {
        const int s = kt & 1;
        if (kt == DM / BK - 1) cp_wait0(); else cp_wait1();
        __syncthreads();
        const uint32_t abase = sb + OFF_A + s * A_STG;
        const uint32_t bbase = sb + OFF_B + s * B_STG;
#pragma unroll
        for (int ks = 0; ks < 4; ks++) {
            uint32_t af[4][4], bf[4][2];
#pragma unroll
            for (int mf = 0; mf < 4; mf++) {
                const uint32_t lin = (uint32_t)(wm + mf * 16 + a_row) * 128u
                                   + (uint32_t)(ks * 2 + a_chk) * 16u;
                ldsm_x4(af[mf][0], af[mf][1], af[mf][2], af[mf][3], abase + SWZ(lin));
            }
#pragma unroll
            for (int nf = 0; nf < 4; nf++) {
                const uint32_t lin = (uint32_t)(wn + nf * 8 + b_row) * 128u
                                   + (uint32_t)(ks * 2 + b_chk) * 16u;
                ldsm_x2(bf[nf][0], bf[nf][1], bbase + SWZ(lin));
            }
#pragma unroll
            for (int mf = 0; mf < 4; mf++)
#pragma unroll
                for (int nf = 0; nf < 4; nf++)
                    mma16816(acc[mf][nf], af[mf], bf[nf]);
        }
        __syncthreads();
        if (kt + 2 < DM / BK) load_tiles(sb, m0, n0, kt + 2, s, tid);
    }

    // epilogue: bias add + screen |v| >= CAND_T into smem list
    float* s_cv = (float*)(smem + OFF_CV);
    int*   s_ci = (int*)(smem + OFF_CI);
    unsigned* s_cnt = (unsigned*)(smem + OFF_CNT);
    unsigned* s_base = (unsigned*)(smem + OFF_BSE);
    __syncthreads();
    const int r0 = lane >> 2, c0 = (lane & 3) * 2;
#pragma unroll
    for (int mf = 0; mf < 4; mf++) {
#pragma unroll
        for (int nf = 0; nf < 4; nf++) {
#pragma unroll
            for (int i = 0; i < 2; i++) {
#pragma unroll
                for (int j = 0; j < 2; j++) {
                    const int gm = m0 + wm + mf * 16 + r0 + i * 8;
                    const int ln = wn + nf * 8 + c0 + j;
                    const float v = acc[mf][nf][i * 2 + j] + sh_bias[ln];
                    if (fabsf(v) >= CAND_T) {
                        unsigned p = atomicAdd(s_cnt, 1u);
                        if (p < BLK_CAP) { s_cv[p] = v; s_ci[p] = (gm << 14) + n0 + ln; }
                    }
                }
            }
        }
    }
    __syncthreads();
    if (tid == 0) {
        unsigned c = min(*s_cnt, (unsigned)BLK_CAP);
        *s_base = atomicAdd(&g_nwide, c);
        *s_cnt = c;
    }
    __syncthreads();
    const unsigned cnt = *s_cnt, base = *s_base;
    for (unsigned i = tid; i < cnt; i += 256) {
        unsigned p = base + i;
        if (p < WCAP) { g_wide_val[p] = s_cv[i]; g_wide_idx[p] = s_ci[i]; }
    }
}

// ------------------------- generic radix hist/scan ---------------------------
template<int MODE>  // 0: wide bf vals, 1: exact narrow vals
__global__ __launch_bounds__(256) void k_histA() {
    __shared__ unsigned sh[2048];
    for (int i = threadIdx.x; i < 2048; i += 256) sh[i] = 0;
    __syncthreads();
    const float* vals = MODE ? g_exact_val : g_wide_val;
    const unsigned n = MODE ? min(g_nnar, (unsigned)NCAP) : min(g_nwide, (unsigned)WCAP);
    const int stride = gridDim.x * blockDim.x;
    for (unsigned i = blockIdx.x * blockDim.x + threadIdx.x; i < n; i += stride)
        atomicAdd(&sh[__float_as_uint(fabsf(vals[i])) >> 21], 1u);
    __syncthreads();
    for (int i = threadIdx.x; i < 2048; i += 256)
        if (sh[i]) atomicAdd(&g_hist1[i], sh[i]);
}
template<int MODE>
__global__ __launch_bounds__(256) void k_histB() {
    __shared__ unsigned sh[2048];
    for (int i = threadIdx.x; i < 2048; i += 256) sh[i] = 0;
    __syncthreads();
    const unsigned b1 = g_b1;
    const float* vals = MODE ? g_exact_val : g_wide_val;
    const unsigned n = MODE ? min(g_nnar, (unsigned)NCAP) : min(g_nwide, (unsigned)WCAP);
    const int stride = gridDim.x * blockDim.x;
    for (unsigned i = blockIdx.x * blockDim.x + threadIdx.x; i < n; i += stride) {
        unsigned u = __float_as_uint(fabsf(vals[i]));
        if ((u >> 21) == b1) atomicAdd(&sh[(u >> 10) & 0x7FF], 1u);
    }
    __syncthreads();
    for (int i = threadIdx.x; i < 2048; i += 256)
        if (sh[i]) atomicAdd(&g_hist2[i], sh[i]);
}
__global__ __launch_bounds__(1024) void k_scanA() {
    __shared__ unsigned q[2048];
    __shared__ unsigned P[1024];
    const int t = threadIdx.x;
    q[t] = g_hist1[2047 - t];
    q[t + 1024] = g_hist1[1023 - t];
    __syncthreads();
    unsigned pv = q[2 * t] + q[2 * t + 1];
    P[t] = pv; __syncthreads();
    for (int off = 1; off < 1024; off <<= 1) {
        unsigned v = (t >= off) ? P[t - off] : 0;
        __syncthreads();
        P[t] += v;
        __syncthreads();
    }
    const unsigned base = t ? P[t - 1] : 0;
    const unsigned K = K_SEL;
    const unsigned Q0 = base + q[2 * t], Q1 = P[t];
    if (Q0 >= K && base < K) { g_b1 = 2047 - 2 * t; g_rem1 = K - (Q0 - q[2 * t]); }
    else if (Q1 >= K && Q0 < K) { g_b1 = 2047 - (2 * t + 1); g_rem1 = K - (Q1 - q[2 * t + 1]); }
}
__global__ __launch_bounds__(1024) void k_scan2g(int mode) {
    __shared__ unsigned q[2048];
    __shared__ unsigned P[1024];
    const int t = threadIdx.x;
    q[t] = g_hist2[2047 - t];
    q[t + 1024] = g_hist2[1023 - t];
    __syncthreads();
    unsigned pv = q[2 * t] + q[2 * t + 1];
    P[t] = pv; __syncthreads();
    for (int off = 1; off < 1024; off <<= 1) {
        unsigned v = (t >= off) ? P[t - off] : 0;
        __syncthreads();
        P[t] += v;
        __syncthreads();
    }
    const unsigned base = t ? P[t - 1] : 0;
    const unsigned K = g_rem1;
    const unsigned Q0 = base + q[2 * t], Q1 = P[t];
    int hit = -1;
    if (Q0 >= K && base < K) hit = 2 * t;
    else if (Q1 >= K && Q0 < K) hit = 2 * t + 1;
    if (hit >= 0) {
        const unsigned u = (g_b1 << 21) | ((unsigned)(2047 - hit) << 10);
        if (mode == 0) g_Tbf = __uint_as_float(u);
        else {
            g_lo = __uint_as_float(u) - NOISE;
            g_hi = __uint_as_float(u + 1024) + NOISE;
        }
    }
}

// ------------------------- narrow filter + group -----------------------------
template<int PASS>
__global__ __launch_bounds__(256) void k_narrow() {
    const float thr = g_Tbf - MARGIN;
    const unsigned n = min(g_nwide, (unsigned)WCAP);
    const int stride = gridDim.x * blockDim.x;
    for (unsigned i = blockIdx.x * blockDim.x + threadIdx.x; i < n; i += stride) {
        if (fabsf(g_wide_val[i]) >= thr) {
            const int idx = g_wide_idx[i];
            const unsigned grp = ((unsigned)idx & (DS - 1)) >> 5;
            if (PASS == 0) atomicAdd(&g_grp_cnt[grp], 1u);
            else {
                unsigned pos = g_grp_base[grp] + atomicAdd(&g_grp_cur[grp], 1u);
                if (pos < NCAP) g_srt_idx[pos] = idx;
            }
        }
    }
}
__global__ void k_grp_scan() {
    __shared__ unsigned s[NGRP];
    const int t = threadIdx.x;
    s[t] = g_grp_cnt[t];
    __syncthreads();
    if (t == 0) {
        unsigned acc = 0;
        for (int i = 0; i < NGRP; i++) { unsigned c = s[i]; s[i] = acc; acc += c; }
        g_nnar = acc;
    }
    __syncthreads();
    g_grp_base[t] = s[t];
}

// ------------------------- exact fp32 recompute (grouped) --------------------
__global__ __launch_bounds__(256)
void k_exact_batch(const float* __restrict__ A, const float* __restrict__ W,
                   const float* __restrict__ bias) {
    extern __shared__ float sw[];   // [32][1025]
    const int g = blockIdx.x, c0 = g * 32;
    const int tid = threadIdx.x;
    const int cl = tid & 31, kr = tid >> 5;
    for (int k = kr; k < DM; k += 8)
        sw[cl * 1025 + k] = W[(size_t)k * DS + c0 + cl];
    __syncthreads();
    const unsigned base = g_grp_base[g], cnt = g_grp_cnt[g];
    const int w = tid >> 5, lane = tid & 31;
    for (unsigned e = w; e < cnt; e += 8) {
        const int idx = g_srt_idx[base + e];
        const int r = idx >> 14, col = idx & (DS - 1);
        const float4* xr = (const float4*)(A + (size_t)r * DM);
        const float* wc = sw + (col - c0) * 1025;
        float s = 0.f;
#pragma unroll
        for (int i = 0; i < 8; i++) {
            const float4 a = xr[lane + 32 * i];
            const int k4 = (lane + 32 * i) * 4;
            s += a.x * wc[k4]; s += a.y * wc[k4 + 1];
            s += a.z * wc[k4 + 2]; s += a.w * wc[k4 + 3];
        }
#pragma unroll
        for (int off = 16; off; off >>= 1) s += __shfl_down_sync(0xffffffffu, s, off);
        if (!lane) g_exact_val[base + e] = s + bias[col];
    }
}

// ------------------------- classify / fp64 rerank / accept -------------------
__global__ __launch_bounds__(256) void k_classify(float* __restrict__ fx) {
    __shared__ unsigned s_in;
    if (threadIdx.x == 0) s_in = 0;
    __syncthreads();
    const float hi = g_hi, lo = g_lo;
    const unsigned n = min(g_nnar, (unsigned)NCAP);
    const int stride = gridDim.x * blockDim.x;
    for (unsigned i = blockIdx.x * blockDim.x + threadIdx.x; i < n; i += stride) {
        const float v = g_exact_val[i];
        const float a = fabsf(v);
        const int idx = g_srt_idx[i];
        if (a >= hi) {
            atomicAdd(&s_in, 1u);
            fx[idx] = v;
            const int row = idx >> 14;
            unsigned slot = atomicAdd(&g_row_cnt[row], 1u);
            if (slot < ROWCAP) {
                g_row_col[row * ROWCAP + slot] = idx & (DS - 1);
                g_row_val[row * ROWCAP + slot] = v;
            }
        } else if (a > lo) {
            unsigned p = atomicAdd(&g_b_cnt, 1u);
            if (p < BCAP) { g_b_idx[p] = idx; g_b_f32[p] = v; }
        }
    }
    __syncthreads();
    if (threadIdx.x == 0 && s_in) atomicAdd(&g_c_in, s_in);
}

__global__ __launch_bounds__(256)
void k_exact64(const float* __restrict__ A, const float* __restrict__ B,
               const float* __restrict__ bias) {
    const int n = min(g_b_cnt, (unsigned)BCAP);
    const int warps = (gridDim.x * blockDim.x) >> 5;
    const int wid = (blockIdx.x * blockDim.x + threadIdx.x) >> 5;
    const int lane = threadIdx.x & 31;
    for (int e = wid; e < n; e += warps) {
        const int idx = g_b_idx[e];
        const int row = idx >> 14, col = idx & (DS - 1);
        const float* xr = A + (size_t)row * DM;
        double s = 0.0;
        for (int m = lane; m < DM; m += 32)
            s += (double)xr[m] * (double)B[(size_t)m * DS + col];
#pragma unroll
        for (int off = 16; off; off >>= 1) s += __shfl_down_sync(0xffffffffu, s, off);
        if (!lane) g_b_v64[e] = fabs(s + (double)bias[col]);
    }
}

__global__ __launch_bounds__(1024) void k_accept(float* __restrict__ fx) {
    const int n = min(g_b_cnt, (unsigned)BCAP);
    const unsigned kp = K_SEL - g_c_in;
    for (int i = threadIdx.x; i < n; i += 1024) {
        const double vi = g_b_v64[i];
        const int ii = g_b_idx[i];
        unsigned rank = 0;
        for (int j = 0; j < n; j++) {
            const double vj = g_b_v64[j];
            rank += (vj > vi) || (vj == vi && g_b_idx[j] < ii);
        }
        if (rank < kp) {
            fx[ii] = g_b_f32[i];
            const int row = ii >> 14;
            unsigned slot = atomicAdd(&g_row_cnt[row], 1u);
            if (slot < ROWCAP) {
                g_row_col[row * ROWCAP + slot] = ii & (DS - 1);
                g_row_val[row * ROWCAP + slot] = g_b_f32[i];
            }
        }
    }
}

// ------------------------- CSR decode ----------------------------------------
__global__ __launch_bounds__(256)
void k_decode(const float* __restrict__ Wd, const float* __restrict__ bdec,
              float* __restrict__ xhat) {
    __shared__ int   s_col[ROWCAP];
    __shared__ float s_val[ROWCAP];
    __shared__ int   s_scol[ROWCAP];
    __shared__ float s_sval[ROWCAP];
    const int b = blockIdx.x, tid = threadIdx.x;
    const int cnt = (int)min(g_row_cnt[b], (unsigned)ROWCAP);
    if (tid < cnt) {
        s_col[tid] = g_row_col[b * ROWCAP + tid];
        s_val[tid] = g_row_val[b * ROWCAP + tid];
    }
    __syncthreads();
    if (tid < cnt) {
        const int ci = s_col[tid];
        int rank = 0;
        for (int j = 0; j < cnt; j++) rank += (s_col[j] < ci);
        s_scol[rank] = ci;
        s_sval[rank] = s_val[tid];
    }
    __syncthreads();
    float4 acc = *(const float4*)(bdec + tid * 4);
    int i = 0;
    for (; i + 4 <= cnt; i += 4) {
        const int c0 = s_scol[i], c1 = s_scol[i+1], c2 = s_scol[i+2], c3 = s_scol[i+3];
        const float v0 = s_sval[i], v1 = s_sval[i+1], v2 = s_sval[i+2], v3 = s_sval[i+3];
        const float4 w0 = *(const float4*)(Wd + (size_t)c0 * DM + tid * 4);
        const float4 w1 = *(const float4*)(Wd + (size_t)c1 * DM + tid * 4);
        const float4 w2 = *(const float4*)(Wd + (size_t)c2 * DM + tid * 4);
        const float4 w3 = *(const float4*)(Wd + (size_t)c3 * DM + tid * 4);
        acc.x += v0*w0.x; acc.y += v0*w0.y; acc.z += v0*w0.z; acc.w += v0*w0.w;
        acc.x += v1*w1.x; acc.y += v1*w1.y; acc.z += v1*w1.z; acc.w += v1*w1.w;
        acc.x += v2*w2.x; acc.y += v2*w2.y; acc.z += v2*w2.z; acc.w += v2*w2.w;
        acc.x += v3*w3.x; acc.y += v3*w3.y; acc.z += v3*w3.z; acc.w += v3*w3.w;
    }
    for (; i < cnt; ++i) {
        const int c0 = s_scol[i];
        const float v0 = s_sval[i];
        const float4 w0 = *(const float4*)(Wd + (size_t)c0 * DM + tid * 4);
        acc.x += v0*w0.x; acc.y += v0*w0.y; acc.z += v0*w0.z; acc.w += v0*w0.w;
    }
    *(float4*)(xhat + (size_t)b * DM + tid * 4) = acc;
}

// ------------------------- host launcher -------------------------------------
extern "C" void kernel_launch(void* const* d_in, const int* in_sizes, int n_in,
                              void* d_out, int out_size) {
    const float* x     = (const float*)d_in[0];
    const float* W_enc = (const float*)d_in[1];
    const float* b_enc = (const float*)d_in[2];
    const float* W_dec = (const float*)d_in[3];
    const float* b_dec = (const float*)d_in[4];

    float* out  = (float*)d_out;
    float* xhat = out;

    static float* g_fb_ptr = nullptr;
    if (!g_fb_ptr) cudaGetSymbolAddress((void**)&g_fb_ptr, g_fx_fallback);
    const long long want = (long long)BATCH * DM + (long long)H_TOTAL;
    float* fx = ((long long)out_size >= want) ? (out + (size_t)BATCH * DM) : g_fb_ptr;

    cudaFuncSetAttribute(k_gemm_bf, cudaFuncAttributeMaxDynamicSharedMemorySize, SMEM_GEMM);
    cudaFuncSetAttribute(k_exact_batch, cudaFuncAttributeMaxDynamicSharedMemorySize, 32 * 1025 * 4);

    k_reset<<<16, 256>>>();
    k_cvt_x<<<1024, 256>>>(x);
    k_cvt_wT<<<dim3(DS / 32, DM / 32), dim3(32, 8)>>>(W_enc);
    k_gemm_bf<<<dim3(DS / BN, BATCH / BM), 256, SMEM_GEMM>>>(b_enc);
    cudaMemsetAsync(fx, 0, (size_t)H_TOTAL * sizeof(float), 0);
    k_histA<0><<<256, 256>>>();
    k_scanA<<<1, 1024>>>();
    k_histB<0><<<256, 256>>>();
    k_scan2g<<<1, 1024>>>(0);
    k_narrow<0><<<256, 256>>>();
    k_grp_scan<<<1, NGRP>>>();
    k_narrow<1><<<256, 256>>>();
    k_exact_batch<<<NGRP, 256, 32 * 1025 * 4>>>(x, W_enc, b_enc);
    k_reset2<<<8, 256>>>();
    k_histA<1><<<256, 256>>>();
    k_scanA<<<1, 1024>>>();
    k_histB<1><<<256, 256>>>();
    k_scan2g<<<1, 1024>>>(1);
    k_classify<<<256, 256>>>(fx);
    k_exact64<<<64, 256>>>(x, W_enc, b_enc);
    k_accept<<<1, 1024>>>(fx);
    k_decode<<<BATCH, 256>>>(W_dec, b_dec, xhat);
}

// round 6
// speedup vs baseline: 5.8342x; 1.1288x over previous
#include <cuda_runtime.h>
#include <cuda_bf16.h>
#include <cstdint>

#define BATCH   4096
#define DM      1024
#define DS      16384
#define K_SEL   131072
#define H_TOTAL 67108864
#define WCAP    (2*1024*1024)
#define NCAP    (512*1024)
#define BCAP    8192
#define NOISE   1.5e-4f
#define MARGIN  0.04f
#define CAND_T  3.9f
#define ROWCAP  96
#define BLK_CAP 1024
#define NGRP    512

// GEMM tiling (sm80-style mma.sync path; tcgen05 unavailable: ptx target sm_100)
#define BM 128
#define BN 128
#define BK 64
#define A_STG 16384
#define B_STG 16384
#define OFF_A    0
#define OFF_B    32768
#define OFF_BIAS 65536
#define OFF_CV   66048
#define OFF_CI   70144
#define OFF_CNT  74240
#define OFF_BSE  74244
#define OFF_HIST 74368
#define SMEM_GEMM (74368 + 8192)

#define SWZ(b) ((b) ^ (((b) >> 3) & 0x70))

// ------------------------- device scratch ------------------------------------
__device__ float          g_fx_fallback[H_TOTAL];
__device__ __nv_bfloat16  g_xb[BATCH * DM];
__device__ __nv_bfloat16  g_wbT[DS * DM];        // [n][k] bf16
__device__ float          g_wide_val[WCAP];
__device__ int            g_wide_idx[WCAP];
__device__ unsigned int   g_nwide;
__device__ unsigned int   g_hist1[2048];
__device__ unsigned int   g_hist2[2048];
__device__ unsigned int   g_b1, g_rem1;
__device__ float          g_Tbf;
__device__ float          g_hi, g_lo;
__device__ unsigned int   g_grp_cnt[NGRP], g_grp_cur[NGRP], g_grp_base[NGRP];
__device__ unsigned int   g_nnar;
__device__ int            g_srt_idx[NCAP];
__device__ float          g_exact_val[NCAP];
__device__ unsigned int   g_c_in, g_b_cnt;
__device__ int            g_b_idx[BCAP];
__device__ float          g_b_f32[BCAP];
__device__ double         g_b_v64[BCAP];
__device__ unsigned int   g_row_cnt[BATCH];
__device__ int            g_row_col[BATCH * ROWCAP];
__device__ float          g_row_val[BATCH * ROWCAP];

// ------------------------- PTX helpers ---------------------------------------
__device__ __forceinline__ uint32_t smem_u32(const void* p) {
    uint32_t a;
    asm("{ .reg .u64 t; cvta.to.shared.u64 t, %1; cvt.u32.u64 %0, t; }" : "=r"(a) : "l"(p));
    return a;
}
__device__ __forceinline__ void cpasync16(uint32_t dst, const void* src) {
    asm volatile("cp.async.cg.shared.global [%0], [%1], 16;" :: "r"(dst), "l"(src) : "memory");
}
__device__ __forceinline__ void cp_commit() { asm volatile("cp.async.commit_group;" ::: "memory"); }
__device__ __forceinline__ void cp_wait1()  { asm volatile("cp.async.wait_group 1;" ::: "memory"); }
__device__ __forceinline__ void cp_wait0()  { asm volatile("cp.async.wait_group 0;" ::: "memory"); }

__device__ __forceinline__ void ldsm_x4(uint32_t& r0, uint32_t& r1, uint32_t& r2, uint32_t& r3,
                                        uint32_t addr) {
    asm volatile("ldmatrix.sync.aligned.m8n8.x4.shared.b16 {%0,%1,%2,%3}, [%4];"
                 : "=r"(r0), "=r"(r1), "=r"(r2), "=r"(r3) : "r"(addr));
}
__device__ __forceinline__ void mma16816(float* d, const uint32_t* a, const uint32_t* b) {
    asm volatile(
        "mma.sync.aligned.m16n8k16.row.col.f32.bf16.bf16.f32 "
        "{%0,%1,%2,%3}, {%4,%5,%6,%7}, {%8,%9}, {%0,%1,%2,%3};"
        : "+f"(d[0]), "+f"(d[1]), "+f"(d[2]), "+f"(d[3])
        : "r"(a[0]), "r"(a[1]), "r"(a[2]), "r"(a[3]), "r"(b[0]), "r"(b[1]));
}

// ------------------------- reset ---------------------------------------------
__global__ void k_reset() {
    int i = blockIdx.x * blockDim.x + threadIdx.x;
    if (i < 2048) { g_hist1[i] = 0; g_hist2[i] = 0; }
    if (i < NGRP) { g_grp_cnt[i] = 0; g_grp_cur[i] = 0; }
    if (i < BATCH) g_row_cnt[i] = 0;
    if (i == 0) { g_nwide = 0; g_nnar = 0; g_c_in = 0; g_b_cnt = 0; }
}
__global__ void k_reset2() {
    int i = blockIdx.x * blockDim.x + threadIdx.x;
    if (i < 2048) { g_hist1[i] = 0; g_hist2[i] = 0; }
}

// ------------------------- converts ------------------------------------------
__global__ void k_cvt_x(const float* __restrict__ x) {
    const int n2 = BATCH * DM / 2;
    const int stride = gridDim.x * blockDim.x;
    __nv_bfloat162* o = (__nv_bfloat162*)g_xb;
    const float2* s = (const float2*)x;
    for (int i = blockIdx.x * blockDim.x + threadIdx.x; i < n2; i += stride)
        o[i] = __float22bfloat162_rn(s[i]);
}
__global__ void k_cvt_wT(const float* __restrict__ W) {
    __shared__ float t[32][33];
    const int n0 = blockIdx.x * 32, k0 = blockIdx.y * 32;
    const int tx = threadIdx.x, ty = threadIdx.y;  // 32 x 8
#pragma unroll
    for (int i = 0; i < 4; i++)
        t[ty + 8 * i][tx] = W[(size_t)(k0 + ty + 8 * i) * DS + n0 + tx];
    __syncthreads();
#pragma unroll
    for (int i = 0; i < 4; i++)
        g_wbT[(size_t)(n0 + ty + 8 * i) * DM + k0 + tx] = __float2bfloat16(t[tx][ty + 8 * i]);
}

// ------------------------- bf16 mma.sync GEMM + screen + hist ----------------
__device__ __forceinline__ void load_tiles(uint32_t sb, int m0, int n0, int kt, int s, int tid) {
    const uint32_t ab = sb + OFF_A + s * A_STG;
#pragma unroll
    for (int i = 0; i < 4; i++) {
        int c = tid + i * 256;
        int row = c >> 3, chunk = c & 7;
        cpasync16(ab + SWZ((uint32_t)row * 128u + (uint32_t)chunk * 16u),
                  g_xb + (size_t)(m0 + row) * DM + kt * BK + chunk * 8);
    }
    const uint32_t bb = sb + OFF_B + s * B_STG;
#pragma unroll
    for (int i = 0; i < 4; i++) {
        int c = tid + i * 256;
        int row = c >> 3, chunk = c & 7;
        cpasync16(bb + SWZ((uint32_t)row * 128u + (uint32_t)chunk * 16u),
                  g_wbT + (size_t)(n0 + row) * DM + kt * BK + chunk * 8);
    }
    cp_commit();
}

__global__ __launch_bounds__(256, 2)
void k_gemm_bf(const float* __restrict__ bias) {
    extern __shared__ char smem[];
    const uint32_t sb = smem_u32(smem);
    const int tid = threadIdx.x, wid = tid >> 5, lane = tid & 31;
    const int m0 = blockIdx.y * BM, n0 = blockIdx.x * BN;
    const int wm = (wid & 1) * 64;     // warp m-offset
    const int wn = (wid >> 1) * 32;    // warp n-offset

    float* sh_bias = (float*)(smem + OFF_BIAS);
    unsigned* sh_hist = (unsigned*)(smem + OFF_HIST);
    if (tid < BN) sh_bias[tid] = bias[n0 + tid];
    if (tid == 0) *(unsigned*)(smem + OFF_CNT) = 0;
    for (int i = tid; i < 2048; i += 256) sh_hist[i] = 0;

    float acc[4][4][4];
#pragma unroll
    for (int mf = 0; mf < 4; mf++)
#pragma unroll
        for (int nf = 0; nf < 4; nf++)
#pragma unroll
            for (int r = 0; r < 4; r++) acc[mf][nf][r] = 0.f;

    load_tiles(sb, m0, n0, 0, 0, tid);
    load_tiles(sb, m0, n0, 1, 1, tid);

    // ldmatrix lane addressing
    const int a_row = (lane & 15);
    const int a_chk = (lane >> 4);
    const int b_mat = lane >> 3;          // matrix index 0..3 for x4
    const int b_sub = (b_mat >> 1) * 8 + (lane & 7);   // row within 16-row pair
    const int b_chk = (b_mat & 1);

    for (int kt = 0; kt < DM / BK; ++kt) {
        const int s = kt & 1;
        if (kt == DM / BK - 1) cp_wait0(); else cp_wait1();
        __syncthreads();
        const uint32_t abase = sb + OFF_A + s * A_STG;
        const uint32_t bbase = sb + OFF_B + s * B_STG;
#pragma unroll
        for (int ks = 0; ks < 4; ks++) {
            uint32_t af[4][4], bf[4][2];
#pragma unroll
            for (int mf = 0; mf < 4; mf++) {
                const uint32_t lin = (uint32_t)(wm + mf * 16 + a_row) * 128u
                                   + (uint32_t)(ks * 2 + a_chk) * 16u;
                ldsm_x4(af[mf][0], af[mf][1], af[mf][2], af[mf][3], abase + SWZ(lin));
            }
#pragma unroll
            for (int nfp = 0; nfp < 2; nfp++) {   // each x4 loads two n-frags
                const uint32_t lin = (uint32_t)(wn + nfp * 16 + b_sub) * 128u
                                   + (uint32_t)(ks * 2 + b_chk) * 16u;
                ldsm_x4(bf[2 * nfp][0], bf[2 * nfp][1],
                        bf[2 * nfp + 1][0], bf[2 * nfp + 1][1], bbase + SWZ(lin));
            }
#pragma unroll
            for (int mf = 0; mf < 4; mf++)
#pragma unroll
                for (int nf = 0; nf < 4; nf++)
                    mma16816(acc[mf][nf], af[mf], bf[nf]);
        }
        __syncthreads();
        if (kt + 2 < DM / BK) load_tiles(sb, m0, n0, kt + 2, s, tid);
    }

    // epilogue: bias add + screen |v| >= CAND_T + fused |v| histogram
    float* s_cv = (float*)(smem + OFF_CV);
    int*   s_ci = (int*)(smem + OFF_CI);
    unsigned* s_cnt = (unsigned*)(smem + OFF_CNT);
    unsigned* s_base = (unsigned*)(smem + OFF_BSE);
    __syncthreads();
    const int r0 = lane >> 2, c0 = (lane & 3) * 2;
#pragma unroll
    for (int mf = 0; mf < 4; mf++) {
#pragma unroll
        for (int nf = 0; nf < 4; nf++) {
#pragma unroll
            for (int i = 0; i < 2; i++) {
#pragma unroll
                for (int j = 0; j < 2; j++) {
                    const int gm = m0 + wm + mf * 16 + r0 + i * 8;
                    const int ln = wn + nf * 8 + c0 + j;
                    const float v = acc[mf][nf][i * 2 + j] + sh_bias[ln];
                    const float a = fabsf(v);
                    if (a >= CAND_T) {
                        atomicAdd(&sh_hist[__float_as_uint(a) >> 21], 1u);
                        unsigned p = atomicAdd(s_cnt, 1u);
                        if (p < BLK_CAP) { s_cv[p] = v; s_ci[p] = (gm << 14) + n0 + ln; }
                    }
                }
            }
        }
    }
    __syncthreads();
    if (tid == 0) {
        unsigned c = min(*s_cnt, (unsigned)BLK_CAP);
        *s_base = atomicAdd(&g_nwide, c);
        *s_cnt = c;
    }
    __syncthreads();
    const unsigned cnt = *s_cnt, base = *s_base;
    for (unsigned i = tid; i < cnt; i += 256) {
        unsigned p = base + i;
        if (p < WCAP) { g_wide_val[p] = s_cv[i]; g_wide_idx[p] = s_ci[i]; }
    }
    for (int i = tid; i < 2048; i += 256)
        if (sh_hist[i]) atomicAdd(&g_hist1[i], sh_hist[i]);
}

// ------------------------- radix hist/scan -----------------------------------
__global__ __launch_bounds__(256) void k_histA1() {
    __shared__ unsigned sh[2048];
    for (int i = threadIdx.x; i < 2048; i += 256) sh[i] = 0;
    __syncthreads();
    const unsigned n = min(g_nnar, (unsigned)NCAP);
    const int stride = gridDim.x * blockDim.x;
    for (unsigned i = blockIdx.x * blockDim.x + threadIdx.x; i < n; i += stride)
        atomicAdd(&sh[__float_as_uint(fabsf(g_exact_val[i])) >> 21], 1u);
    __syncthreads();
    for (int i = threadIdx.x; i < 2048; i += 256)
        if (sh[i]) atomicAdd(&g_hist1[i], sh[i]);
}
template<int MODE>
__global__ __launch_bounds__(256) void k_histB() {
    __shared__ unsigned sh[2048];
    for (int i = threadIdx.x; i < 2048; i += 256) sh[i] = 0;
    __syncthreads();
    const unsigned b1 = g_b1;
    const float* vals = MODE ? g_exact_val : g_wide_val;
    const unsigned n = MODE ? min(g_nnar, (unsigned)NCAP) : min(g_nwide, (unsigned)WCAP);
    const int stride = gridDim.x * blockDim.x;
    for (unsigned i = blockIdx.x * blockDim.x + threadIdx.x; i < n; i += stride) {
        unsigned u = __float_as_uint(fabsf(vals[i]));
        if ((u >> 21) == b1) atomicAdd(&sh[(u >> 10) & 0x7FF], 1u);
    }
    __syncthreads();
    for (int i = threadIdx.x; i < 2048; i += 256)
        if (sh[i]) atomicAdd(&g_hist2[i], sh[i]);
}
__global__ __launch_bounds__(1024) void k_scanA() {
    __shared__ unsigned q[2048];
    __shared__ unsigned P[1024];
    const int t = threadIdx.x;
    q[t] = g_hist1[2047 - t];
    q[t + 1024] = g_hist1[1023 - t];
    __syncthreads();
    unsigned pv = q[2 * t] + q[2 * t + 1];
    P[t] = pv; __syncthreads();
    for (int off = 1; off < 1024; off <<= 1) {
        unsigned v = (t >= off) ? P[t - off] : 0;
        __syncthreads();
        P[t] += v;
        __syncthreads();
    }
    const unsigned base = t ? P[t - 1] : 0;
    const unsigned K = K_SEL;
    const unsigned Q0 = base + q[2 * t], Q1 = P[t];
    if (Q0 >= K && base < K) { g_b1 = 2047 - 2 * t; g_rem1 = K - (Q0 - q[2 * t]); }
    else if (Q1 >= K && Q0 < K) { g_b1 = 2047 - (2 * t + 1); g_rem1 = K - (Q1 - q[2 * t + 1]); }
}
__global__ __launch_bounds__(1024) void k_scan2g(int mode) {
    __shared__ unsigned q[2048];
    __shared__ unsigned P[1024];
    const int t = threadIdx.x;
    q[t] = g_hist2[2047 - t];
    q[t + 1024] = g_hist2[1023 - t];
    __syncthreads();
    unsigned pv = q[2 * t] + q[2 * t + 1];
    P[t] = pv; __syncthreads();
    for (int off = 1; off < 1024; off <<= 1) {
        unsigned v = (t >= off) ? P[t - off] : 0;
        __syncthreads();
        P[t] += v;
        __syncthreads();
    }
    const unsigned base = t ? P[t - 1] : 0;
    const unsigned K = g_rem1;
    const unsigned Q0 = base + q[2 * t], Q1 = P[t];
    int hit = -1;
    if (Q0 >= K && base < K) hit = 2 * t;
    else if (Q1 >= K && Q0 < K) hit = 2 * t + 1;
    if (hit >= 0) {
        const unsigned u = (g_b1 << 21) | ((unsigned)(2047 - hit) << 10);
        if (mode == 0) g_Tbf = __uint_as_float(u);
        else {
            g_lo = __uint_as_float(u) - NOISE;
            g_hi = __uint_as_float(u + 1024) + NOISE;
        }
    }
}

// ------------------------- narrow filter + group -----------------------------
template<int PASS>
__global__ __launch_bounds__(256) void k_narrow() {
    const float thr = g_Tbf - MARGIN;
    const unsigned n = min(g_nwide, (unsigned)WCAP);
    const int stride = gridDim.x * blockDim.x;
    for (unsigned i = blockIdx.x * blockDim.x + threadIdx.x; i < n; i += stride) {
        if (fabsf(g_wide_val[i]) >= thr) {
            const int idx = g_wide_idx[i];
            const unsigned grp = ((unsigned)idx & (DS - 1)) >> 5;
            if (PASS == 0) atomicAdd(&g_grp_cnt[grp], 1u);
            else {
                unsigned pos = g_grp_base[grp] + atomicAdd(&g_grp_cur[grp], 1u);
                if (pos < NCAP) g_srt_idx[pos] = idx;
            }
        }
    }
}
__global__ void k_grp_scan() {
    __shared__ unsigned s[NGRP];
    const int t = threadIdx.x;
    s[t] = g_grp_cnt[t];
    __syncthreads();
    if (t == 0) {
        unsigned acc = 0;
        for (int i = 0; i < NGRP; i++) { unsigned c = s[i]; s[i] = acc; acc += c; }
        g_nnar = acc;
    }
    __syncthreads();
    g_grp_base[t] = s[t];
}

// ------------------------- exact fp32 recompute (grouped) --------------------
__global__ __launch_bounds__(512)
void k_exact_batch(const float* __restrict__ A, const float* __restrict__ W,
                   const float* __restrict__ bias) {
    extern __shared__ float sw[];   // [32][1025]
    const int g = blockIdx.x, c0 = g * 32;
    const int tid = threadIdx.x;
    const int cl = tid & 31, kr = tid >> 5;   // 16 k-rows
    for (int k = kr; k < DM; k += 16)
        sw[cl * 1025 + k] = W[(size_t)k * DS + c0 + cl];
    __syncthreads();
    const unsigned base = g_grp_base[g], cnt = g_grp_cnt[g];
    const int w = tid >> 5, lane = tid & 31;
    for (unsigned e = w; e < cnt; e += 16) {
        const int idx = g_srt_idx[base + e];
        const int r = idx >> 14, col = idx & (DS - 1);
        const float4* xr = (const float4*)(A + (size_t)r * DM);
        const float* wc = sw + (col - c0) * 1025;
        float s = 0.f;
#pragma unroll
        for (int i = 0; i < 8; i++) {
            const float4 a = xr[lane + 32 * i];
            const int k4 = (lane + 32 * i) * 4;
            s += a.x * wc[k4]; s += a.y * wc[k4 + 1];
            s += a.z * wc[k4 + 2]; s += a.w * wc[k4 + 3];
        }
#pragma unroll
        for (int off = 16; off; off >>= 1) s += __shfl_down_sync(0xffffffffu, s, off);
        if (!lane) g_exact_val[base + e] = s + bias[col];
    }
}

// ------------------------- classify / fp64 rerank / accept -------------------
__global__ __launch_bounds__(256) void k_classify(float* __restrict__ fx) {
    __shared__ unsigned s_in;
    if (threadIdx.x == 0) s_in = 0;
    __syncthreads();
    const float hi = g_hi, lo = g_lo;
    const unsigned n = min(g_nnar, (unsigned)NCAP);
    const int stride = gridDim.x * blockDim.x;
    for (unsigned i = blockIdx.x * blockDim.x + threadIdx.x; i < n; i += stride) {
        const float v = g_exact_val[i];
        const float a = fabsf(v);
        const int idx = g_srt_idx[i];
        if (a >= hi) {
            atomicAdd(&s_in, 1u);
            fx[idx] = v;
            const int row = idx >> 14;
            unsigned slot = atomicAdd(&g_row_cnt[row], 1u);
            if (slot < ROWCAP) {
                g_row_col[row * ROWCAP + slot] = idx & (DS - 1);
                g_row_val[row * ROWCAP + slot] = v;
            }
        } else if (a > lo) {
            unsigned p = atomicAdd(&g_b_cnt, 1u);
            if (p < BCAP) { g_b_idx[p] = idx; g_b_f32[p] = v; }
        }
    }
    __syncthreads();
    if (threadIdx.x == 0 && s_in) atomicAdd(&g_c_in, s_in);
}

__global__ __launch_bounds__(256)
void k_exact64(const float* __restrict__ A, const float* __restrict__ B,
               const float* __restrict__ bias) {
    const int n = min(g_b_cnt, (unsigned)BCAP);
    const int warps = (gridDim.x * blockDim.x) >> 5;
    const int wid = (blockIdx.x * blockDim.x + threadIdx.x) >> 5;
    const int lane = threadIdx.x & 31;
    for (int e = wid; e < n; e += warps) {
        const int idx = g_b_idx[e];
        const int row = idx >> 14, col = idx & (DS - 1);
        const float* xr = A + (size_t)row * DM;
        double s = 0.0;
        for (int m = lane; m < DM; m += 32)
            s += (double)xr[m] * (double)B[(size_t)m * DS + col];
#pragma unroll
        for (int off = 16; off; off >>= 1) s += __shfl_down_sync(0xffffffffu, s, off);
        if (!lane) g_b_v64[e] = fabs(s + (double)bias[col]);
    }
}

__global__ __launch_bounds__(1024) void k_accept(float* __restrict__ fx) {
    const int n = min(g_b_cnt, (unsigned)BCAP);
    const unsigned kp = K_SEL - g_c_in;
    for (int i = threadIdx.x; i < n; i += 1024) {
        const double vi = g_b_v64[i];
        const int ii = g_b_idx[i];
        unsigned rank = 0;
        for (int j = 0; j < n; j++) {
            const double vj = g_b_v64[j];
            rank += (vj > vi) || (vj == vi && g_b_idx[j] < ii);
        }
        if (rank < kp) {
            fx[ii] = g_b_f32[i];
            const int row = ii >> 14;
            unsigned slot = atomicAdd(&g_row_cnt[row], 1u);
            if (slot < ROWCAP) {
                g_row_col[row * ROWCAP + slot] = ii & (DS - 1);
                g_row_val[row * ROWCAP + slot] = g_b_f32[i];
            }
        }
    }
}

// ------------------------- CSR decode ----------------------------------------
__global__ __launch_bounds__(256)
void k_decode(const float* __restrict__ Wd, const float* __restrict__ bdec,
              float* __restrict__ xhat) {
    __shared__ int   s_col[ROWCAP];
    __shared__ float s_val[ROWCAP];
    __shared__ int   s_scol[ROWCAP];
    __shared__ float s_sval[ROWCAP];
    const int b = blockIdx.x, tid = threadIdx.x;
    const int cnt = (int)min(g_row_cnt[b], (unsigned)ROWCAP);
    if (tid < cnt) {
        s_col[tid] = g_row_col[b * ROWCAP + tid];
        s_val[tid] = g_row_val[b * ROWCAP + tid];
    }
    __syncthreads();
    if (tid < cnt) {
        const int ci = s_col[tid];
        int rank = 0;
        for (int j = 0; j < cnt; j++) rank += (s_col[j] < ci);
        s_scol[rank] = ci;
        s_sval[rank] = s_val[tid];
    }
    __syncthreads();
    float4 acc = *(const float4*)(bdec + tid * 4);
    int i = 0;
    for (; i + 4 <= cnt; i += 4) {
        const int c0 = s_scol[i], c1 = s_scol[i+1], c2 = s_scol[i+2], c3 = s_scol[i+3];
        const float v0 = s_sval[i], v1 = s_sval[i+1], v2 = s_sval[i+2], v3 = s_sval[i+3];
        const float4 w0 = *(const float4*)(Wd + (size_t)c0 * DM + tid * 4);
        const float4 w1 = *(const float4*)(Wd + (size_t)c1 * DM + tid * 4);
        const float4 w2 = *(const float4*)(Wd + (size_t)c2 * DM + tid * 4);
        const float4 w3 = *(const float4*)(Wd + (size_t)c3 * DM + tid * 4);
        acc.x += v0*w0.x; acc.y += v0*w0.y; acc.z += v0*w0.z; acc.w += v0*w0.w;
        acc.x += v1*w1.x; acc.y += v1*w1.y; acc.z += v1*w1.z; acc.w += v1*w1.w;
        acc.x += v2*w2.x; acc.y += v2*w2.y; acc.z += v2*w2.z; acc.w += v2*w2.w;
        acc.x += v3*w3.x; acc.y += v3*w3.y; acc.z += v3*w3.z; acc.w += v3*w3.w;
    }
    for (; i < cnt; ++i) {
        const int c0 = s_scol[i];
        const float v0 = s_sval[i];
        const float4 w0 = *(const float4*)(Wd + (size_t)c0 * DM + tid * 4);
        acc.x += v0*w0.x; acc.y += v0*w0.y; acc.z += v0*w0.z; acc.w += v0*w0.w;
    }
    *(float4*)(xhat + (size_t)b * DM + tid * 4) = acc;
}

// ------------------------- host launcher -------------------------------------
extern "C" void kernel_launch(void* const* d_in, const int* in_sizes, int n_in,
                              void* d_out, int out_size) {
    const float* x     = (const float*)d_in[0];
    const float* W_enc = (const float*)d_in[1];
    const float* b_enc = (const float*)d_in[2];
    const float* W_dec = (const float*)d_in[3];
    const float* b_dec = (const float*)d_in[4];

    float* out  = (float*)d_out;
    float* xhat = out;

    static float* g_fb_ptr = nullptr;
    static cudaStream_t s2 = nullptr;
    static cudaEvent_t ev_fork = nullptr, ev_join = nullptr;
    if (!g_fb_ptr) {
        cudaGetSymbolAddress((void**)&g_fb_ptr, g_fx_fallback);
        cudaStreamCreateWithFlags(&s2, cudaStreamNonBlocking);
        cudaEventCreateWithFlags(&ev_fork, cudaEventDisableTiming);
        cudaEventCreateWithFlags(&ev_join, cudaEventDisableTiming);
    }
    const long long want = (long long)BATCH * DM + (long long)H_TOTAL;
    float* fx = ((long long)out_size >= want) ? (out + (size_t)BATCH * DM) : g_fb_ptr;

    cudaFuncSetAttribute(k_gemm_bf, cudaFuncAttributeMaxDynamicSharedMemorySize, SMEM_GEMM);
    cudaFuncSetAttribute(k_exact_batch, cudaFuncAttributeMaxDynamicSharedMemorySize, 32 * 1025 * 4);

    k_reset<<<16, 256>>>();

    // fork: overlap the 256 MB f_x memset with the GEMM on a second stream
    cudaEventRecord(ev_fork, 0);
    cudaStreamWaitEvent(s2, ev_fork, 0);
    cudaMemsetAsync(fx, 0, (size_t)H_TOTAL * sizeof(float), s2);
    cudaEventRecord(ev_join, s2);

    k_cvt_x<<<1024, 256>>>(x);
    k_cvt_wT<<<dim3(DS / 32, DM / 32), dim3(32, 8)>>>(W_enc);
    k_gemm_bf<<<dim3(DS / BN, BATCH / BM), 256, SMEM_GEMM>>>(b_enc);
    k_scanA<<<1, 1024>>>();
    k_histB<0><<<256, 256>>>();
    k_scan2g<<<1, 1024>>>(0);
    k_narrow<0><<<256, 256>>>();
    k_grp_scan<<<1, NGRP>>>();
    k_narrow<1><<<256, 256>>>();
    k_exact_batch<<<NGRP, 512, 32 * 1025 * 4>>>(x, W_enc, b_enc);
    k_reset2<<<8, 256>>>();
    k_histA1<<<256, 256>>>();
    k_scanA<<<1, 1024>>>();
    k_histB<1><<<256, 256>>>();
    k_scan2g<<<1, 1024>>>(1);

    cudaStreamWaitEvent(0, ev_join, 0);   // join memset before writing fx
    k_classify<<<256, 256>>>(fx);
    k_exact64<<<64, 256>>>(x, W_enc, b_enc);
    k_accept<<<1, 1024>>>(fx);
    k_decode<<<BATCH, 256>>>(W_dec, b_dec, xhat);
}

// round 7
// speedup vs baseline: 6.1778x; 1.0589x over previous
#include <cuda_runtime.h>
#include <cuda_bf16.h>
#include <cstdint>

#define BATCH   4096
#define DM      1024
#define DS      16384
#define K_SEL   131072
#define H_TOTAL 67108864
#define WCAP    (2*1024*1024)
#define BCAP    8192
#define NOISE   1.5e-4f
#define MARGIN  0.04f
#define CAND_T  3.9f
#define ROWCAP  96
#define BLK_CAP 1024
#define NGRP    512
#define GCAP    1024          // bucket slots per 32-col group (mean ~354)
#define HWIN    504           // float-bin window base for smem hists

// GEMM tiling: 3-stage cp.async pipeline, BK=64
#define BM 128
#define BN 128
#define BK 64
#define STG_SZ   16384
#define OFF_A    0
#define OFF_B    49152
#define OFF_BIAS 98304
#define OFF_CV   98816
#define OFF_CI   102912
#define OFF_CNT  107008
#define OFF_BSE  107012
#define OFF_HIST 107016
#define SMEM_GEMM 107392

#define SWZ(b) ((b) ^ (((b) >> 3) & 0x70))

// ------------------------- device scratch ------------------------------------
__device__ float          g_fx_fallback[H_TOTAL];
__device__ __nv_bfloat16  g_xb[BATCH * DM];
__device__ __nv_bfloat16  g_wbT[DS * DM];        // [n][k] bf16
__device__ float          g_wide_val[WCAP];
__device__ int            g_wide_idx[WCAP];
__device__ unsigned int   g_nwide;
__device__ unsigned int   g_hist1[2048];         // bf |h| coarse (GEMM-fused)
__device__ unsigned int   g_hist2[2048];         // bf refine
__device__ unsigned int   g_hist3[2048];         // exact coarse (exact-fused)
__device__ unsigned int   g_hist4[2048];         // exact refine
__device__ unsigned int   g_b1, g_rem1;
__device__ float          g_Tbf;
__device__ float          g_hi, g_lo;
__device__ unsigned int   g_grp_cnt[NGRP];
__device__ int            g_bk_idx[NGRP * GCAP];
__device__ float          g_exact_val[NGRP * GCAP];
__device__ unsigned int   g_c_in, g_b_cnt;
__device__ int            g_b_idx[BCAP];
__device__ float          g_b_f32[BCAP];
__device__ double         g_b_v64[BCAP];
__device__ unsigned int   g_row_cnt[BATCH];
__device__ int            g_row_col[BATCH * ROWCAP];
__device__ float          g_row_val[BATCH * ROWCAP];

// ------------------------- PTX helpers ---------------------------------------
__device__ __forceinline__ uint32_t smem_u32(const void* p) {
    uint32_t a;
    asm("{ .reg .u64 t; cvta.to.shared.u64 t, %1; cvt.u32.u64 %0, t; }" : "=r"(a) : "l"(p));
    return a;
}
__device__ __forceinline__ void cpasync16(uint32_t dst, const void* src) {
    asm volatile("cp.async.cg.shared.global [%0], [%1], 16;" :: "r"(dst), "l"(src) : "memory");
}
__device__ __forceinline__ void cp_commit() { asm volatile("cp.async.commit_group;" ::: "memory"); }
__device__ __forceinline__ void cp_wait1()  { asm volatile("cp.async.wait_group 1;" ::: "memory"); }
__device__ __forceinline__ void cp_wait0()  { asm volatile("cp.async.wait_group 0;" ::: "memory"); }

__device__ __forceinline__ void ldsm_x4(uint32_t& r0, uint32_t& r1, uint32_t& r2, uint32_t& r3,
                                        uint32_t addr) {
    asm volatile("ldmatrix.sync.aligned.m8n8.x4.shared.b16 {%0,%1,%2,%3}, [%4];"
                 : "=r"(r0), "=r"(r1), "=r"(r2), "=r"(r3) : "r"(addr));
}
__device__ __forceinline__ void mma16816(float* d, const uint32_t* a, const uint32_t* b) {
    asm volatile(
        "mma.sync.aligned.m16n8k16.row.col.f32.bf16.bf16.f32 "
        "{%0,%1,%2,%3}, {%4,%5,%6,%7}, {%8,%9}, {%0,%1,%2,%3};"
        : "+f"(d[0]), "+f"(d[1]), "+f"(d[2]), "+f"(d[3])
        : "r"(a[0]), "r"(a[1]), "r"(a[2]), "r"(a[3]), "r"(b[0]), "r"(b[1]));
}

// ------------------------- reset ---------------------------------------------
__global__ void k_reset() {
    int i = blockIdx.x * blockDim.x + threadIdx.x;
    if (i < 2048) { g_hist1[i] = 0; g_hist2[i] = 0; g_hist3[i] = 0; g_hist4[i] = 0; }
    if (i < NGRP) g_grp_cnt[i] = 0;
    if (i < BATCH) g_row_cnt[i] = 0;
    if (i == 0) { g_nwide = 0; g_c_in = 0; g_b_cnt = 0; }
}

// ------------------------- converts ------------------------------------------
__global__ void k_cvt_x(const float* __restrict__ x) {
    const int n2 = BATCH * DM / 2;
    const int stride = gridDim.x * blockDim.x;
    __nv_bfloat162* o = (__nv_bfloat162*)g_xb;
    const float2* s = (const float2*)x;
    for (int i = blockIdx.x * blockDim.x + threadIdx.x; i < n2; i += stride)
        o[i] = __float22bfloat162_rn(s[i]);
}
__global__ void k_cvt_wT(const float* __restrict__ W) {
    __shared__ float t[32][33];
    const int n0 = blockIdx.x * 32, k0 = blockIdx.y * 32;
    const int tx = threadIdx.x, ty = threadIdx.y;  // 32 x 8
#pragma unroll
    for (int i = 0; i < 4; i++)
        t[ty + 8 * i][tx] = W[(size_t)(k0 + ty + 8 * i) * DS + n0 + tx];
    __syncthreads();
#pragma unroll
    for (int i = 0; i < 4; i++)
        g_wbT[(size_t)(n0 + ty + 8 * i) * DM + k0 + tx] = __float2bfloat16(t[tx][ty + 8 * i]);
}

// ------------------------- bf16 mma.sync GEMM, 3-stage pipeline --------------
__device__ __forceinline__ void load_tiles(uint32_t sb, int m0, int n0, int kt, int s, int tid) {
    const uint32_t ab = sb + OFF_A + s * STG_SZ;
#pragma unroll
    for (int i = 0; i < 4; i++) {
        int c = tid + i * 256;
        int row = c >> 3, chunk = c & 7;
        cpasync16(ab + SWZ((uint32_t)row * 128u + (uint32_t)chunk * 16u),
                  g_xb + (size_t)(m0 + row) * DM + kt * BK + chunk * 8);
    }
    const uint32_t bb = sb + OFF_B + s * STG_SZ;
#pragma unroll
    for (int i = 0; i < 4; i++) {
        int c = tid + i * 256;
        int row = c >> 3, chunk = c & 7;
        cpasync16(bb + SWZ((uint32_t)row * 128u + (uint32_t)chunk * 16u),
                  g_wbT + (size_t)(n0 + row) * DM + kt * BK + chunk * 8);
    }
    cp_commit();
}

__global__ __launch_bounds__(256, 2)
void k_gemm_bf(const float* __restrict__ bias) {
    extern __shared__ char smem[];
    const uint32_t sb = smem_u32(smem);
    const int tid = threadIdx.x, wid = tid >> 5, lane = tid & 31;
    const int m0 = blockIdx.y * BM, n0 = blockIdx.x * BN;
    const int wm = (wid & 1) * 64;
    const int wn = (wid >> 1) * 32;

    float* sh_bias = (float*)(smem + OFF_BIAS);
    unsigned* sh_hist = (unsigned*)(smem + OFF_HIST);
    if (tid < BN) sh_bias[tid] = bias[n0 + tid];
    if (tid == 0) *(unsigned*)(smem + OFF_CNT) = 0;
    if (tid < 64) sh_hist[tid] = 0;

    float acc[4][4][4];
#pragma unroll
    for (int mf = 0; mf < 4; mf++)
#pragma unroll
        for (int nf = 0; nf < 4; nf++)
#pragma unroll
            for (int r = 0; r < 4; r++) acc[mf][nf][r] = 0.f;

    load_tiles(sb, m0, n0, 0, 0, tid);
    load_tiles(sb, m0, n0, 1, 1, tid);

    const int a_row = (lane & 15);
    const int a_chk = (lane >> 4);
    const int b_mat = lane >> 3;
    const int b_sub = (b_mat >> 1) * 8 + (lane & 7);
    const int b_chk = (b_mat & 1);

    int s = 0, s2 = 2;   // compute stage, load-target stage
    for (int kt = 0; kt < DM / BK; ++kt) {
        if (kt == DM / BK - 1) cp_wait0(); else cp_wait1();
        __syncthreads();
        // safe: all warps finished compute kt-1 (buffer s2) before this barrier
        if (kt + 2 < DM / BK) load_tiles(sb, m0, n0, kt + 2, s2, tid);
        const uint32_t abase = sb + OFF_A + s * STG_SZ;
        const uint32_t bbase = sb + OFF_B + s * STG_SZ;
#pragma unroll
        for (int ks = 0; ks < 4; ks++) {
            uint32_t af[4][4], bf[4][2];
#pragma unroll
            for (int mf = 0; mf < 4; mf++) {
                const uint32_t lin = (uint32_t)(wm + mf * 16 + a_row) * 128u
                                   + (uint32_t)(ks * 2 + a_chk) * 16u;
                ldsm_x4(af[mf][0], af[mf][1], af[mf][2], af[mf][3], abase + SWZ(lin));
            }
#pragma unroll
            for (int nfp = 0; nfp < 2; nfp++) {
                const uint32_t lin = (uint32_t)(wn + nfp * 16 + b_sub) * 128u
                                   + (uint32_t)(ks * 2 + b_chk) * 16u;
                ldsm_x4(bf[2 * nfp][0], bf[2 * nfp][1],
                        bf[2 * nfp + 1][0], bf[2 * nfp + 1][1], bbase + SWZ(lin));
            }
#pragma unroll
            for (int mf = 0; mf < 4; mf++)
#pragma unroll
                for (int nf = 0; nf < 4; nf++)
                    mma16816(acc[mf][nf], af[mf], bf[nf]);
        }
        s = (s == 2) ? 0 : s + 1;
        s2 = (s2 == 2) ? 0 : s2 + 1;
    }

    // epilogue: bias add + screen + fused windowed histogram
    float* s_cv = (float*)(smem + OFF_CV);
    int*   s_ci = (int*)(smem + OFF_CI);
    unsigned* s_cnt = (unsigned*)(smem + OFF_CNT);
    unsigned* s_base = (unsigned*)(smem + OFF_BSE);
    __syncthreads();
    const int r0 = lane >> 2, c0 = (lane & 3) * 2;
#pragma unroll
    for (int mf = 0; mf < 4; mf++) {
#pragma unroll
        for (int nf = 0; nf < 4; nf++) {
#pragma unroll
            for (int i = 0; i < 2; i++) {
#pragma unroll
                for (int j = 0; j < 2; j++) {
                    const int gm = m0 + wm + mf * 16 + r0 + i * 8;
                    const int ln = wn + nf * 8 + c0 + j;
                    const float v = acc[mf][nf][i * 2 + j] + sh_bias[ln];
                    const float a = fabsf(v);
                    if (a >= CAND_T) {
                        int b = (int)(__float_as_uint(a) >> 21) - HWIN;
                        b = max(0, min(63, b));
                        atomicAdd(&sh_hist[b], 1u);
                        unsigned p = atomicAdd(s_cnt, 1u);
                        if (p < BLK_CAP) { s_cv[p] = v; s_ci[p] = (gm << 14) + n0 + ln; }
                    }
                }
            }
        }
    }
    __syncthreads();
    if (tid == 0) {
        unsigned c = min(*s_cnt, (unsigned)BLK_CAP);
        *s_base = atomicAdd(&g_nwide, c);
        *s_cnt = c;
    }
    __syncthreads();
    const unsigned cnt = *s_cnt, base = *s_base;
    for (unsigned i = tid; i < cnt; i += 256) {
        unsigned p = base + i;
        if (p < WCAP) { g_wide_val[p] = s_cv[i]; g_wide_idx[p] = s_ci[i]; }
    }
    if (tid < 64 && sh_hist[tid]) atomicAdd(&g_hist1[HWIN + tid], sh_hist[tid]);
}

// ------------------------- radix scans ---------------------------------------
__global__ __launch_bounds__(1024) void k_scanA(const unsigned* __restrict__ hist, unsigned K) {
    __shared__ unsigned q[2048];
    __shared__ unsigned P[1024];
    const int t = threadIdx.x;
    q[t] = hist[2047 - t];
    q[t + 1024] = hist[1023 - t];
    __syncthreads();
    unsigned pv = q[2 * t] + q[2 * t + 1];
    P[t] = pv; __syncthreads();
    for (int off = 1; off < 1024; off <<= 1) {
        unsigned v = (t >= off) ? P[t - off] : 0;
        __syncthreads();
        P[t] += v;
        __syncthreads();
    }
    const unsigned base = t ? P[t - 1] : 0;
    const unsigned Q0 = base + q[2 * t], Q1 = P[t];
    if (Q0 >= K && base < K) { g_b1 = 2047 - 2 * t; g_rem1 = K - (Q0 - q[2 * t]); }
    else if (Q1 >= K && Q0 < K) { g_b1 = 2047 - (2 * t + 1); g_rem1 = K - (Q1 - q[2 * t + 1]); }
}
__global__ __launch_bounds__(1024) void k_scan2g(const unsigned* __restrict__ hist, int mode) {
    __shared__ unsigned q[2048];
    __shared__ unsigned P[1024];
    const int t = threadIdx.x;
    q[t] = hist[2047 - t];
    q[t + 1024] = hist[1023 - t];
    __syncthreads();
    unsigned pv = q[2 * t] + q[2 * t + 1];
    P[t] = pv; __syncthreads();
    for (int off = 1; off < 1024; off <<= 1) {
        unsigned v = (t >= off) ? P[t - off] : 0;
        __syncthreads();
        P[t] += v;
        __syncthreads();
    }
    const unsigned base = t ? P[t - 1] : 0;
    const unsigned K = g_rem1;
    const unsigned Q0 = base + q[2 * t], Q1 = P[t];
    int hit = -1;
    if (Q0 >= K && base < K) hit = 2 * t;
    else if (Q1 >= K && Q0 < K) hit = 2 * t + 1;
    if (hit >= 0) {
        const unsigned u = (g_b1 << 21) | ((unsigned)(2047 - hit) << 10);
        if (mode == 0) g_Tbf = __uint_as_float(u);
        else {
            g_lo = __uint_as_float(u) - NOISE;
            g_hi = __uint_as_float(u + 1024) + NOISE;
        }
    }
}

// bf refine pass over wide set
__global__ __launch_bounds__(256) void k_histB0() {
    __shared__ unsigned sh[2048];
    for (int i = threadIdx.x; i < 2048; i += 256) sh[i] = 0;
    __syncthreads();
    const unsigned b1 = g_b1;
    const unsigned n = min(g_nwide, (unsigned)WCAP);
    const int stride = gridDim.x * blockDim.x;
    for (unsigned i = blockIdx.x * blockDim.x + threadIdx.x; i < n; i += stride) {
        unsigned u = __float_as_uint(fabsf(g_wide_val[i]));
        if ((u >> 21) == b1) atomicAdd(&sh[(u >> 10) & 0x7FF], 1u);
    }
    __syncthreads();
    for (int i = threadIdx.x; i < 2048; i += 256)
        if (sh[i]) atomicAdd(&g_hist2[i], sh[i]);
}

// ------------------------- single-pass bucketed narrow filter ----------------
__global__ __launch_bounds__(256) void k_bucket() {
    const float thr = g_Tbf - MARGIN;
    const unsigned n = min(g_nwide, (unsigned)WCAP);
    const int stride = gridDim.x * blockDim.x;
    for (unsigned i = blockIdx.x * blockDim.x + threadIdx.x; i < n; i += stride) {
        if (fabsf(g_wide_val[i]) >= thr) {
            const int idx = g_wide_idx[i];
            const unsigned g = ((unsigned)idx & (DS - 1)) >> 5;
            unsigned slot = atomicAdd(&g_grp_cnt[g], 1u);
            if (slot < GCAP) g_bk_idx[g * GCAP + slot] = idx;
        }
    }
}

// ------------------------- exact fp32 recompute + fused hist -----------------
__global__ __launch_bounds__(512)
void k_exact_batch(const float* __restrict__ A, const float* __restrict__ W,
                   const float* __restrict__ bias) {
    extern __shared__ float sw[];   // [32][1025]
    __shared__ unsigned sh_h[64];
    const int g = blockIdx.x, c0 = g * 32;
    const int tid = threadIdx.x;
    const int cl = tid & 31, kr = tid >> 5;
    if (tid < 64) sh_h[tid] = 0;
    for (int k = kr; k < DM; k += 16)
        sw[cl * 1025 + k] = W[(size_t)k * DS + c0 + cl];
    __syncthreads();
    const unsigned base = (unsigned)g * GCAP;
    const unsigned cnt = min(g_grp_cnt[g], (unsigned)GCAP);
    const int w = tid >> 5, lane = tid & 31;
    for (unsigned e = w; e < cnt; e += 16) {
        const int idx = g_bk_idx[base + e];
        const int r = idx >> 14, col = idx & (DS - 1);
        const float4* xr = (const float4*)(A + (size_t)r * DM);
        const float* wc = sw + (col - c0) * 1025;
        float s = 0.f;
#pragma unroll
        for (int i = 0; i < 8; i++) {
            const float4 a = xr[lane + 32 * i];
            const int k4 = (lane + 32 * i) * 4;
            s += a.x * wc[k4]; s += a.y * wc[k4 + 1];
            s += a.z * wc[k4 + 2]; s += a.w * wc[k4 + 3];
        }
#pragma unroll
        for (int off = 16; off; off >>= 1) s += __shfl_down_sync(0xffffffffu, s, off);
        if (!lane) {
            const float v = s + bias[col];
            g_exact_val[base + e] = v;
            int b = (int)(__float_as_uint(fabsf(v)) >> 21) - HWIN;
            b = max(0, min(63, b));
            atomicAdd(&sh_h[b], 1u);
        }
    }
    __syncthreads();
    if (tid < 64 && sh_h[tid]) atomicAdd(&g_hist3[HWIN + tid], sh_h[tid]);
}

// exact refine pass over buckets
__global__ __launch_bounds__(256) void k_histB1() {
    __shared__ unsigned sh[2048];
    for (int i = threadIdx.x; i < 2048; i += 256) sh[i] = 0;
    __syncthreads();
    const unsigned b1 = g_b1;
    const unsigned n = NGRP * GCAP;
    const int stride = gridDim.x * blockDim.x;
    for (unsigned i = blockIdx.x * blockDim.x + threadIdx.x; i < n; i += stride) {
        const unsigned g = i >> 10, e = i & (GCAP - 1);
        if (e < min(g_grp_cnt[g], (unsigned)GCAP)) {
            unsigned u = __float_as_uint(fabsf(g_exact_val[i]));
            if ((u >> 21) == b1) atomicAdd(&sh[(u >> 10) & 0x7FF], 1u);
        }
    }
    __syncthreads();
    for (int i = threadIdx.x; i < 2048; i += 256)
        if (sh[i]) atomicAdd(&g_hist4[i], sh[i]);
}

// ------------------------- classify / fp64 rerank / accept -------------------
__global__ __launch_bounds__(256) void k_classify(float* __restrict__ fx) {
    __shared__ unsigned s_in;
    if (threadIdx.x == 0) s_in = 0;
    __syncthreads();
    const float hi = g_hi, lo = g_lo;
    const unsigned n = NGRP * GCAP;
    const int stride = gridDim.x * blockDim.x;
    for (unsigned i = blockIdx.x * blockDim.x + threadIdx.x; i < n; i += stride) {
        const unsigned g = i >> 10, e = i & (GCAP - 1);
        if (e >= min(g_grp_cnt[g], (unsigned)GCAP)) continue;
        const float v = g_exact_val[i];
        const float a = fabsf(v);
        const int idx = g_bk_idx[i];
        if (a >= hi) {
            atomicAdd(&s_in, 1u);
            fx[idx] = v;
            const int row = idx >> 14;
            unsigned slot = atomicAdd(&g_row_cnt[row], 1u);
            if (slot < ROWCAP) {
                g_row_col[row * ROWCAP + slot] = idx & (DS - 1);
                g_row_val[row * ROWCAP + slot] = v;
            }
        } else if (a > lo) {
            unsigned p = atomicAdd(&g_b_cnt, 1u);
            if (p < BCAP) { g_b_idx[p] = idx; g_b_f32[p] = v; }
        }
    }
    __syncthreads();
    if (threadIdx.x == 0 && s_in) atomicAdd(&g_c_in, s_in);
}

__global__ __launch_bounds__(256)
void k_exact64(const float* __restrict__ A, const float* __restrict__ B,
               const float* __restrict__ bias) {
    const int n = min(g_b_cnt, (unsigned)BCAP);
    const int warps = (gridDim.x * blockDim.x) >> 5;
    const int wid = (blockIdx.x * blockDim.x + threadIdx.x) >> 5;
    const int lane = threadIdx.x & 31;
    for (int e = wid; e < n; e += warps) {
        const int idx = g_b_idx[e];
        const int row = idx >> 14, col = idx & (DS - 1);
        const float* xr = A + (size_t)row * DM;
        double s = 0.0;
        for (int m = lane; m < DM; m += 32)
            s += (double)xr[m] * (double)B[(size_t)m * DS + col];
#pragma unroll
        for (int off = 16; off; off >>= 1) s += __shfl_down_sync(0xffffffffu, s, off);
        if (!lane) g_b_v64[e] = fabs(s + (double)bias[col]);
    }
}

__global__ __launch_bounds__(1024) void k_accept(float* __restrict__ fx) {
    const int n = min(g_b_cnt, (unsigned)BCAP);
    const unsigned kp = K_SEL - g_c_in;
    for (int i = threadIdx.x; i < n; i += 1024) {
        const double vi = g_b_v64[i];
        const int ii = g_b_idx[i];
        unsigned rank = 0;
        for (int j = 0; j < n; j++) {
            const double vj = g_b_v64[j];
            rank += (vj > vi) || (vj == vi && g_b_idx[j] < ii);
        }
        if (rank < kp) {
            fx[ii] = g_b_f32[i];
            const int row = ii >> 14;
            unsigned slot = atomicAdd(&g_row_cnt[row], 1u);
            if (slot < ROWCAP) {
                g_row_col[row * ROWCAP + slot] = ii & (DS - 1);
                g_row_val[row * ROWCAP + slot] = g_b_f32[i];
            }
        }
    }
}

// ------------------------- CSR decode ----------------------------------------
__global__ __launch_bounds__(256)
void k_decode(const float* __restrict__ Wd, const float* __restrict__ bdec,
              float* __restrict__ xhat) {
    __shared__ int   s_col[ROWCAP];
    __shared__ float s_val[ROWCAP];
    __shared__ int   s_scol[ROWCAP];
    __shared__ float s_sval[ROWCAP];
    const int b = blockIdx.x, tid = threadIdx.x;
    const int cnt = (int)min(g_row_cnt[b], (unsigned)ROWCAP);
    if (tid < cnt) {
        s_col[tid] = g_row_col[b * ROWCAP + tid];
        s_val[tid] = g_row_val[b * ROWCAP + tid];
    }
    __syncthreads();
    if (tid < cnt) {
        const int ci = s_col[tid];
        int rank = 0;
        for (int j = 0; j < cnt; j++) rank += (s_col[j] < ci);
        s_scol[rank] = ci;
        s_sval[rank] = s_val[tid];
    }
    __syncthreads();
    float4 acc = *(const float4*)(bdec + tid * 4);
    int i = 0;
    for (; i + 4 <= cnt; i += 4) {
        const int c0 = s_scol[i], c1 = s_scol[i+1], c2 = s_scol[i+2], c3 = s_scol[i+3];
        const float v0 = s_sval[i], v1 = s_sval[i+1], v2 = s_sval[i+2], v3 = s_sval[i+3];
        const float4 w0 = *(const float4*)(Wd + (size_t)c0 * DM + tid * 4);
        const float4 w1 = *(const float4*)(Wd + (size_t)c1 * DM + tid * 4);
        const float4 w2 = *(const float4*)(Wd + (size_t)c2 * DM + tid * 4);
        const float4 w3 = *(const float4*)(Wd + (size_t)c3 * DM + tid * 4);
        acc.x += v0*w0.x; acc.y += v0*w0.y; acc.z += v0*w0.z; acc.w += v0*w0.w;
        acc.x += v1*w1.x; acc.y += v1*w1.y; acc.z += v1*w1.z; acc.w += v1*w1.w;
        acc.x += v2*w2.x; acc.y += v2*w2.y; acc.z += v2*w2.z; acc.w += v2*w2.w;
        acc.x += v3*w3.x; acc.y += v3*w3.y; acc.z += v3*w3.z; acc.w += v3*w3.w;
    }
    for (; i < cnt; ++i) {
        const int c0 = s_scol[i];
        const float v0 = s_sval[i];
        const float4 w0 = *(const float4*)(Wd + (size_t)c0 * DM + tid * 4);
        acc.x += v0*w0.x; acc.y += v0*w0.y; acc.z += v0*w0.z; acc.w += v0*w0.w;
    }
    *(float4*)(xhat + (size_t)b * DM + tid * 4) = acc;
}

// ------------------------- host launcher -------------------------------------
extern "C" void kernel_launch(void* const* d_in, const int* in_sizes, int n_in,
                              void* d_out, int out_size) {
    const float* x     = (const float*)d_in[0];
    const float* W_enc = (const float*)d_in[1];
    const float* b_enc = (const float*)d_in[2];
    const float* W_dec = (const float*)d_in[3];
    const float* b_dec = (const float*)d_in[4];

    float* out  = (float*)d_out;
    float* xhat = out;

    static float* g_fb_ptr = nullptr;
    static unsigned *h1 = nullptr, *h2 = nullptr, *h3 = nullptr, *h4 = nullptr;
    static cudaStream_t s2 = nullptr;
    static cudaEvent_t ev_fork = nullptr, ev_x = nullptr, ev_join = nullptr;
    if (!g_fb_ptr) {
        cudaGetSymbolAddress((void**)&g_fb_ptr, g_fx_fallback);
        cudaGetSymbolAddress((void**)&h1, g_hist1);
        cudaGetSymbolAddress((void**)&h2, g_hist2);
        cudaGetSymbolAddress((void**)&h3, g_hist3);
        cudaGetSymbolAddress((void**)&h4, g_hist4);
        cudaStreamCreateWithFlags(&s2, cudaStreamNonBlocking);
        cudaEventCreateWithFlags(&ev_fork, cudaEventDisableTiming);
        cudaEventCreateWithFlags(&ev_x, cudaEventDisableTiming);
        cudaEventCreateWithFlags(&ev_join, cudaEventDisableTiming);
    }
    const long long want = (long long)BATCH * DM + (long long)H_TOTAL;
    float* fx = ((long long)out_size >= want) ? (out + (size_t)BATCH * DM) : g_fb_ptr;

    cudaFuncSetAttribute(k_gemm_bf, cudaFuncAttributeMaxDynamicSharedMemorySize, SMEM_GEMM);
    cudaFuncSetAttribute(k_exact_batch, cudaFuncAttributeMaxDynamicSharedMemorySize, 32 * 1025 * 4);

    k_reset<<<16, 256>>>();

    // fork: s2 does x-convert (joined before GEMM) then the 256 MB f_x memset
    // (joined before classify), both overlapped with main-stream work
    cudaEventRecord(ev_fork, 0);
    cudaStreamWaitEvent(s2, ev_fork, 0);
    k_cvt_x<<<1024, 256, 0, s2>>>(x);
    cudaEventRecord(ev_x, s2);
    cudaMemsetAsync(fx, 0, (size_t)H_TOTAL * sizeof(float), s2);
    cudaEventRecord(ev_join, s2);

    k_cvt_wT<<<dim3(DS / 32, DM / 32), dim3(32, 8)>>>(W_enc);
    cudaStreamWaitEvent(0, ev_x, 0);
    k_gemm_bf<<<dim3(DS / BN, BATCH / BM), 256, SMEM_GEMM>>>(b_enc);

    k_scanA<<<1, 1024>>>(h1, K_SEL);
    k_histB0<<<256, 256>>>();
    k_scan2g<<<1, 1024>>>(h2, 0);
    k_bucket<<<256, 256>>>();
    k_exact_batch<<<NGRP, 512, 32 * 1025 * 4>>>(x, W_enc, b_enc);
    k_scanA<<<1, 1024>>>(h3, K_SEL);
    k_histB1<<<512, 256>>>();
    k_scan2g<<<1, 1024>>>(h4, 1);

    cudaStreamWaitEvent(0, ev_join, 0);
    k_classify<<<256, 256>>>(fx);
    k_exact64<<<64, 256>>>(x, W_enc, b_enc);
    k_accept<<<1, 1024>>>(fx);
    k_decode<<<BATCH, 256>>>(W_dec, b_dec, xhat);
}